// round 2
// baseline (speedup 1.0000x reference)
#include <cuda_runtime.h>
#include <math.h>

// ---------------- problem constants ----------------
#define BATCH_MAX 65536
#define DIMV 64
#define CTXD 384
#define HIDD 128
#define NPR 5
#define MEMN 10
#define ROWS 16
#define GRID_A 148
#define GRID_B 296
#define EPSV 1e-8f

// ---------------- device scratch (static, allocation-free) ----------------
__device__ float g_e[BATCH_MAX * DIMV];     // emotion MLP output (pre-stress)
__device__ float g_partials[GRID_A];        // per-block stress partial sums
__device__ float g_stress;                  // total stress
__device__ float g_gic[2][192];             // folded GRU gi constants (f, r)

// ---------------- smem layout kernel A (float offsets) ----------------
#define A_SWCTX   0                     // [384][68]  transposed ctx_w
#define A_SWE1    26112                 // [64][132]  transposed emo_w1
#define A_SWE2    34560                 // [128][68]  transposed emo_w2
#define A_SIW     43264                 // [5][128]   ideal_w
#define A_SPE     43904                 // [5][64]    prime_embeds
#define A_SCB     44224                 // [64] ctx_b
#define A_SB1     44288                 // [128] emo_b1
#define A_SB2     44416                 // [64] emo_b2
#define A_SIB     44480                 // [8] ideal_b
#define A_SPI     44488                 // [64] prev_ideal
#define A_SCX     44552                 // [16][384] context tile
#define A_STH     50696                 // [16][64] theta tile
#define A_SCTXO   51720                 // [16][64] ctx output tile
#define A_SH1     52744                 // [16][128] emo hidden tile
#define A_SLG     54792                 // [16][8] ideal logits
#define A_SRED    54920                 // [256] reduce
#define A_TOTAL   55176
#define SMEM_A    (A_TOTAL * 4)

// ---------------- smem layout kernel B ----------------
#define B_SWIH    0                     // [66][196] transposed w_ih cols 64..129
#define B_SWHH    12936                 // [64][196] transposed w_hh
#define B_SGIC    25480                 // [192]
#define B_SX      25672                 // [16][68]  (e rows + res + omega)
#define B_SH      26760                 // [16][64]  h_prev rows
#define B_TOTAL   27784
#define SMEM_B    (B_TOTAL * 4)

// ===================================================================
// Kernel A: ctx matvec, ideal softmax, theta_ideal, emotion MLP,
//           res / omega / stress partials
// ===================================================================
extern "C" __global__ void __launch_bounds__(256)
kA(const float* __restrict__ theta, const float* __restrict__ context,
   const float* __restrict__ ctx_w, const float* __restrict__ ctx_b,
   const float* __restrict__ emo_w1, const float* __restrict__ emo_b1,
   const float* __restrict__ emo_w2, const float* __restrict__ emo_b2,
   const float* __restrict__ prime_embeds, const float* __restrict__ ideal_w,
   const float* __restrict__ ideal_b, const float* __restrict__ prev_ideal,
   const float* __restrict__ freq_w, const float* __restrict__ freq_b,
   float* __restrict__ out_res, float* __restrict__ out_om,
   float* __restrict__ out_pw, int ntiles)
{
    extern __shared__ float sm[];
    const int t = threadIdx.x;

    // ---- stage weights (transposed where the compute loop needs it) ----
    for (int i = t; i < 64 * 384; i += 256) {         // ctx_w[d][k] -> [k][68]+d
        int d = i / 384, k = i % 384;
        sm[A_SWCTX + k * 68 + d] = ctx_w[i];
    }
    for (int i = t; i < 128 * 64; i += 256) {         // emo_w1[j][d] -> [d][132]+j
        int j = i / 64, d = i % 64;
        sm[A_SWE1 + d * 132 + j] = emo_w1[i];
    }
    for (int i = t; i < 64 * 128; i += 256) {         // emo_w2[d][j] -> [j][68]+d
        int d = i / 128, j = i % 128;
        sm[A_SWE2 + j * 68 + d] = emo_w2[i];
    }
    for (int i = t; i < 5 * 128; i += 256) sm[A_SIW + i] = ideal_w[i];
    for (int i = t; i < 5 * 64;  i += 256) sm[A_SPE + i] = prime_embeds[i];
    if (t < 64)  sm[A_SCB + t] = ctx_b[t];
    if (t < 128) sm[A_SB1 + t] = emo_b1[t];
    if (t < 64)  sm[A_SB2 + t] = emo_b2[t];
    if (t < 5)   sm[A_SIB + t] = ideal_b[t];
    if (t < 64)  sm[A_SPI + t] = prev_ideal[t];
    __syncthreads();

    const float fw = freq_w[0], fb = freq_b[0];
    const int r  = t >> 4;        // row in tile (0..15)
    const int dq = t & 15;        // output quad (0..15)
    float st_acc = 0.0f;

    for (int tile = blockIdx.x; tile < ntiles; tile += gridDim.x) {
        __syncthreads();   // protect tile buffers from previous iteration readers
        const int row0 = tile * ROWS;

        // ---- stage context + theta rows (flat, coalesced) ----
        {
            const float4* cx4 = (const float4*)(context + (size_t)row0 * CTXD);
            float4* s4 = (float4*)(sm + A_SCX);
            for (int i = t; i < ROWS * CTXD / 4; i += 256) s4[i] = cx4[i];
            const float4* th4 = (const float4*)(theta + (size_t)row0 * DIMV);
            float4* s4b = (float4*)(sm + A_STH);
            for (int i = t; i < ROWS * DIMV / 4; i += 256) s4b[i] = th4[i];
        }
        __syncthreads();

        const float* xr  = sm + A_SCX + r * CTXD;
        const float* thr = sm + A_STH + r * DIMV;

        // ---- ctx = context @ ctx_w^T + ctx_b  (4 outputs per thread) ----
        {
            float4 acc = *(const float4*)(sm + A_SCB + dq * 4);
            #pragma unroll 4
            for (int k = 0; k < CTXD; k++) {
                float x = xr[k];
                float4 w = *(const float4*)(sm + A_SWCTX + k * 68 + dq * 4);
                acc.x = fmaf(x, w.x, acc.x); acc.y = fmaf(x, w.y, acc.y);
                acc.z = fmaf(x, w.z, acc.z); acc.w = fmaf(x, w.w, acc.w);
            }
            *(float4*)(sm + A_SCTXO + r * DIMV + dq * 4) = acc;
        }

        // ---- emo hidden h1 = tanh(theta @ w1^T + b1), j = dq*4+e and 64+dq*4+e ----
        {
            float4 a1 = *(const float4*)(sm + A_SB1 + dq * 4);
            float4 a2 = *(const float4*)(sm + A_SB1 + 64 + dq * 4);
            #pragma unroll 4
            for (int k = 0; k < DIMV; k++) {
                float x = thr[k];
                float4 w1 = *(const float4*)(sm + A_SWE1 + k * 132 + dq * 4);
                float4 w2 = *(const float4*)(sm + A_SWE1 + k * 132 + 64 + dq * 4);
                a1.x = fmaf(x, w1.x, a1.x); a1.y = fmaf(x, w1.y, a1.y);
                a1.z = fmaf(x, w1.z, a1.z); a1.w = fmaf(x, w1.w, a1.w);
                a2.x = fmaf(x, w2.x, a2.x); a2.y = fmaf(x, w2.y, a2.y);
                a2.z = fmaf(x, w2.z, a2.z); a2.w = fmaf(x, w2.w, a2.w);
            }
            float* h1 = sm + A_SH1 + r * HIDD;
            h1[dq * 4 + 0] = tanhf(a1.x); h1[dq * 4 + 1] = tanhf(a1.y);
            h1[dq * 4 + 2] = tanhf(a1.z); h1[dq * 4 + 3] = tanhf(a1.w);
            h1[64 + dq * 4 + 0] = tanhf(a2.x); h1[64 + dq * 4 + 1] = tanhf(a2.y);
            h1[64 + dq * 4 + 2] = tanhf(a2.z); h1[64 + dq * 4 + 3] = tanhf(a2.w);
        }
        __syncthreads();

        // ---- ideal logits (5 lanes per row) ----
        if (dq < NPR) {
            const float* w = sm + A_SIW + dq * 128;
            const float* cr = sm + A_SCTXO + r * DIMV;
            float l = sm[A_SIB + dq];
            #pragma unroll 8
            for (int k = 0; k < DIMV; k++) l = fmaf(thr[k], w[k], l);
            #pragma unroll 8
            for (int k = 0; k < DIMV; k++) l = fmaf(cr[k], w[64 + k], l);
            sm[A_SLG + r * 8 + dq] = l;
        }
        __syncthreads();

        // ---- softmax over 5 (redundant per lane), theta_ideal quad ----
        float pw[NPR];
        {
            float l[NPR], m = -1e30f;
            #pragma unroll
            for (int p = 0; p < NPR; p++) { l[p] = sm[A_SLG + r * 8 + p]; m = fmaxf(m, l[p]); }
            float s = 0.0f;
            #pragma unroll
            for (int p = 0; p < NPR; p++) { pw[p] = expf(l[p] - m); s += pw[p]; }
            float inv = 1.0f / s;
            #pragma unroll
            for (int p = 0; p < NPR; p++) pw[p] *= inv;
            if (dq < NPR) out_pw[(size_t)(row0 + r) * NPR + dq] = pw[dq];
        }
        float ti4[4];
        #pragma unroll
        for (int e = 0; e < 4; e++) {
            int d = dq * 4 + e;
            float v = 0.0f;
            #pragma unroll
            for (int p = 0; p < NPR; p++) v = fmaf(pw[p], sm[A_SPE + p * 64 + d], v);
            ti4[e] = v;
        }

        // ---- emotion output e = relu(h1 @ w2^T + b2) -> scratch ----
        {
            float4 ea = *(const float4*)(sm + A_SB2 + dq * 4);
            const float* h1 = sm + A_SH1 + r * HIDD;
            #pragma unroll 4
            for (int k = 0; k < HIDD; k++) {
                float x = h1[k];
                float4 w = *(const float4*)(sm + A_SWE2 + k * 68 + dq * 4);
                ea.x = fmaf(x, w.x, ea.x); ea.y = fmaf(x, w.y, ea.y);
                ea.z = fmaf(x, w.z, ea.z); ea.w = fmaf(x, w.w, ea.w);
            }
            float4 ev;
            ev.x = fmaxf(ea.x, 0.0f); ev.y = fmaxf(ea.y, 0.0f);
            ev.z = fmaxf(ea.z, 0.0f); ev.w = fmaxf(ea.w, 0.0f);
            *(float4*)(g_e + (size_t)(row0 + r) * DIMV + dq * 4) = ev;
        }

        // ---- reductions: norms / dot / stress / freq ----
        {
            float th2 = 0, ti2 = 0, dot = 0, st = 0, fr = 0;
            #pragma unroll
            for (int e = 0; e < 4; e++) {
                int d = dq * 4 + e;
                float tv = thr[d], iv = ti4[e];
                th2 = fmaf(tv, tv, th2);
                ti2 = fmaf(iv, iv, ti2);
                dot = fmaf(tv, iv, dot);
                float dd = tv - iv; st = fmaf(dd, dd, st);
                float df = iv - sm[A_SPI + d]; fr = fmaf(df, df, fr);
            }
            st_acc += st;                          // element-level partial, no dedup needed
            #pragma unroll
            for (int o = 1; o < 16; o <<= 1) {
                th2 += __shfl_xor_sync(0xffffffffu, th2, o);
                ti2 += __shfl_xor_sync(0xffffffffu, ti2, o);
                dot += __shfl_xor_sync(0xffffffffu, dot, o);
                fr  += __shfl_xor_sync(0xffffffffu, fr,  o);
            }
            if (dq == 0) {
                float na = sqrtf(th2), nb = sqrtf(ti2);
                float t1 = dot / ((na + EPSV) * (nb + EPSV));
                float den = fmaxf((na / (na + EPSV)) * (nb / (nb + EPSV)), EPSV);
                out_res[row0 + r] = t1 / den;
                float fq = sqrtf(fr);
                out_om[row0 + r] = tanhf(fmaf(fq, fw, fb)) * (1.0f + 0.1f * sinf(fq));
            }
        }
    }

    // ---- block-level stress reduction -> per-block slot ----
    __syncthreads();
    sm[A_SRED + t] = st_acc;
    __syncthreads();
    for (int o = 128; o > 0; o >>= 1) {
        if (t < o) sm[A_SRED + t] += sm[A_SRED + t + o];
        __syncthreads();
    }
    if (t == 0) g_partials[blockIdx.x] = sm[A_SRED];
}

// ===================================================================
// Kernel C: stress total, o_vec, folded gi constants (both directions)
// ===================================================================
extern "C" __global__ void
kC(const float* __restrict__ tw, const float* __restrict__ memory,
   const float* __restrict__ ipw, const float* __restrict__ ipb,
   const float* __restrict__ outw, const float* __restrict__ outb,
   const float* __restrict__ wih_f, const float* __restrict__ bih_f,
   const float* __restrict__ wih_r, const float* __restrict__ bih_r)
{
    __shared__ float attn[MEMN], mt[DIMV], vv[DIMV], ov[DIMV], stress_s;
    const int t = threadIdx.x;
    if (t == 0) {
        float m = -1e30f;
        for (int i = 0; i < MEMN; i++) m = fmaxf(m, tw[i]);
        float s = 0, ex[MEMN];
        for (int i = 0; i < MEMN; i++) { ex[i] = expf(tw[i] - m); s += ex[i]; }
        for (int i = 0; i < MEMN; i++) attn[i] = ex[i] / s;
        float acc = 0;
        for (int i = 0; i < GRID_A; i++) acc += g_partials[i];
        g_stress = acc; stress_s = acc;
    }
    __syncthreads();
    if (t < DIMV) {
        float s = 0;
        for (int m = 0; m < MEMN; m++) s = fmaf(attn[m], memory[m * DIMV + t], s);
        mt[t] = s;
    }
    __syncthreads();
    if (t < DIMV) {
        float s = ipb[2 * DIMV + t];
        for (int d = 0; d < DIMV; d++) s = fmaf(mt[d], ipw[(2 * DIMV + t) * DIMV + d], s);
        vv[t] = s;
    }
    __syncthreads();
    if (t < DIMV) {
        float s = outb[t];
        for (int i = 0; i < DIMV; i++) s = fmaf(vv[i], outw[t * DIMV + i], s);
        ov[t] = s;
    }
    __syncthreads();
    if (t < 192) {
        float sc = 0.001f * stress_s;
        float gf = bih_f[t], gr = bih_r[t];
        for (int k = 0; k < DIMV; k++) {
            gf = fmaf(ov[k], wih_f[t * 130 + k], gf);
            gr = fmaf(ov[k], wih_r[t * 130 + k], gr);
        }
        float sf = 0, sr = 0;
        for (int k = 64; k < 128; k++) { sf += wih_f[t * 130 + k]; sr += wih_r[t * 130 + k]; }
        g_gic[0][t] = fmaf(sc, sf, gf);
        g_gic[1][t] = fmaf(sc, sr, gr);
    }
}

// ===================================================================
// Kernel B: one GRU direction. dir=0 forward (also writes theta_next,
// e_theta), dir=1 reverse.
// ===================================================================
extern "C" __global__ void __launch_bounds__(256)
kB(const float* __restrict__ wih, const float* __restrict__ whh,
   const float* __restrict__ bhh, const float* __restrict__ hprev,
   const float* __restrict__ theta, const float* __restrict__ res_in,
   const float* __restrict__ om_in, float* __restrict__ hout,
   float* __restrict__ thout, float* __restrict__ eout,
   int ntiles, int dir)
{
    extern __shared__ float sm[];
    const int t = threadIdx.x;

    // stage transposed weights: gi columns 64..129 -> rows 0..65, whh -> [k][196]
    for (int i = t; i < 192 * 66; i += 256) {
        int j = i / 66, c = i % 66;
        sm[B_SWIH + c * 196 + j] = wih[j * 130 + 64 + c];
    }
    for (int i = t; i < 192 * 64; i += 256) {
        int j = i / 64, c = i % 64;
        sm[B_SWHH + c * 196 + j] = whh[j * 64 + c];
    }
    if (t < 192) sm[B_SGIC + t] = g_gic[dir][t];
    __syncthreads();

    const float sc = 0.001f * g_stress;
    const int r  = t >> 4;
    const int jq = t & 15;
    const float lam = 0.7f, oml = 1.0f - 0.7f;

    for (int tile = blockIdx.x; tile < ntiles; tile += gridDim.x) {
        __syncthreads();
        const int row0 = tile * ROWS;

        for (int i = t; i < ROWS * DIMV; i += 256) {
            int rr = i >> 6, c = i & 63;
            sm[B_SX + rr * 68 + c] = g_e[(size_t)row0 * DIMV + i];
            sm[B_SH + rr * 64 + c] = hprev[(size_t)row0 * DIMV + i];
        }
        if (t < ROWS) {
            sm[B_SX + t * 68 + 64] = res_in[row0 + t];
            sm[B_SX + t * 68 + 65] = om_in[row0 + t];
        }
        __syncthreads();

        float gi[3][4], gh[3][4];
        #pragma unroll
        for (int g = 0; g < 3; g++) {
            float4 a = *(const float4*)(sm + B_SGIC + g * 64 + jq * 4);
            gi[g][0] = a.x; gi[g][1] = a.y; gi[g][2] = a.z; gi[g][3] = a.w;
            float4 b4 = *(const float4*)(bhh + g * 64 + jq * 4);
            gh[g][0] = b4.x; gh[g][1] = b4.y; gh[g][2] = b4.z; gh[g][3] = b4.w;
        }

        const float* xr = sm + B_SX + r * 68;
        const float* hr = sm + B_SH + r * 64;

        #pragma unroll 2
        for (int k = 0; k < 64; k++) {
            float xv = xr[k], hv = hr[k];
            #pragma unroll
            for (int g = 0; g < 3; g++) {
                float4 wi = *(const float4*)(sm + B_SWIH + k * 196 + g * 64 + jq * 4);
                float4 wh = *(const float4*)(sm + B_SWHH + k * 196 + g * 64 + jq * 4);
                gi[g][0] = fmaf(xv, wi.x, gi[g][0]); gi[g][1] = fmaf(xv, wi.y, gi[g][1]);
                gi[g][2] = fmaf(xv, wi.z, gi[g][2]); gi[g][3] = fmaf(xv, wi.w, gi[g][3]);
                gh[g][0] = fmaf(hv, wh.x, gh[g][0]); gh[g][1] = fmaf(hv, wh.y, gh[g][1]);
                gh[g][2] = fmaf(hv, wh.z, gh[g][2]); gh[g][3] = fmaf(hv, wh.w, gh[g][3]);
            }
        }
        #pragma unroll
        for (int k = 64; k < 66; k++) {          // res, omega columns
            float xv = xr[k];
            #pragma unroll
            for (int g = 0; g < 3; g++) {
                float4 wi = *(const float4*)(sm + B_SWIH + k * 196 + g * 64 + jq * 4);
                gi[g][0] = fmaf(xv, wi.x, gi[g][0]); gi[g][1] = fmaf(xv, wi.y, gi[g][1]);
                gi[g][2] = fmaf(xv, wi.z, gi[g][2]); gi[g][3] = fmaf(xv, wi.w, gi[g][3]);
            }
        }

        float4 hn4;
        float* hn = (float*)&hn4;
        #pragma unroll
        for (int e = 0; e < 4; e++) {
            float rg = 1.0f / (1.0f + expf(-(gi[0][e] + gh[0][e])));
            float zg = 1.0f / (1.0f + expf(-(gi[1][e] + gh[1][e])));
            float ng = tanhf(fmaf(rg, gh[2][e], gi[2][e]));
            float hv = hr[jq * 4 + e];
            hn[e] = fmaf(zg, hv - ng, ng);   // (1-z)*n + z*h
        }
        const size_t ob = (size_t)(row0 + r) * DIMV + jq * 4;
        *(float4*)(hout + ob) = hn4;
        if (dir == 0) {
            float4 th = *(const float4*)(theta + ob);
            float4 tn;
            tn.x = fmaf(lam, hn4.x, oml * th.x); tn.y = fmaf(lam, hn4.y, oml * th.y);
            tn.z = fmaf(lam, hn4.z, oml * th.z); tn.w = fmaf(lam, hn4.w, oml * th.w);
            *(float4*)(thout + ob) = tn;
            float4 ev = *(const float4*)(xr + jq * 4);
            ev.x += sc; ev.y += sc; ev.z += sc; ev.w += sc;
            *(float4*)(eout + ob) = ev;
        }
    }
}

// ===================================================================
// launch
// ===================================================================
extern "C" void kernel_launch(void* const* d_in, const int* in_sizes, int n_in,
                              void* d_out, int out_size)
{
    const float* theta     = (const float*)d_in[0];
    const float* context   = (const float*)d_in[1];
    const float* h_prev    = (const float*)d_in[2];
    const float* memory    = (const float*)d_in[3];
    const float* tw        = (const float*)d_in[4];
    const float* ipw       = (const float*)d_in[5];
    const float* ipb       = (const float*)d_in[6];
    const float* outw      = (const float*)d_in[7];
    const float* outb      = (const float*)d_in[8];
    const float* emo_w1    = (const float*)d_in[9];
    const float* emo_b1    = (const float*)d_in[10];
    const float* emo_w2    = (const float*)d_in[11];
    const float* emo_b2    = (const float*)d_in[12];
    const float* prime_emb = (const float*)d_in[13];
    const float* ctx_w     = (const float*)d_in[14];
    const float* ctx_b     = (const float*)d_in[15];
    const float* ideal_w   = (const float*)d_in[16];
    const float* ideal_b   = (const float*)d_in[17];
    const float* wih_f     = (const float*)d_in[18];
    const float* whh_f     = (const float*)d_in[19];
    const float* bih_f     = (const float*)d_in[20];
    const float* bhh_f     = (const float*)d_in[21];
    const float* wih_r     = (const float*)d_in[22];
    const float* whh_r     = (const float*)d_in[23];
    const float* bih_r     = (const float*)d_in[24];
    const float* bhh_r     = (const float*)d_in[25];
    const float* freq_w    = (const float*)d_in[26];
    const float* freq_b    = (const float*)d_in[27];
    const float* prev_id   = (const float*)d_in[28];

    const int B = in_sizes[0] / DIMV;
    const int ntiles = B / ROWS;

    float* out = (float*)d_out;
    float* o_thn = out;
    float* o_h   = out + (size_t)B * DIMV;        // h_next[0], then h_next[1]
    float* o_e   = out + (size_t)3 * B * DIMV;
    float* o_res = out + (size_t)4 * B * DIMV;
    float* o_om  = o_res + B;
    float* o_pw  = o_om + B;

    cudaFuncSetAttribute((const void*)kA, cudaFuncAttributeMaxDynamicSharedMemorySize, SMEM_A);
    cudaFuncSetAttribute((const void*)kB, cudaFuncAttributeMaxDynamicSharedMemorySize, SMEM_B);

    kA<<<GRID_A, 256, SMEM_A>>>(theta, context, ctx_w, ctx_b, emo_w1, emo_b1,
                                emo_w2, emo_b2, prime_emb, ideal_w, ideal_b,
                                prev_id, freq_w, freq_b, o_res, o_om, o_pw, ntiles);
    kC<<<1, 192>>>(tw, memory, ipw, ipb, outw, outb, wih_f, bih_f, wih_r, bih_r);
    kB<<<GRID_B, 256, SMEM_B>>>(wih_f, whh_f, bhh_f, h_prev, theta, o_res, o_om,
                                o_h, o_thn, o_e, ntiles, 0);
    kB<<<GRID_B, 256, SMEM_B>>>(wih_r, whh_r, bhh_r, h_prev + (size_t)B * DIMV,
                                theta, o_res, o_om, o_h + (size_t)B * DIMV,
                                o_thn, o_e, ntiles, 1);
}

// round 4
// speedup vs baseline: 1.8124x; 1.8124x over previous
#include <cuda_runtime.h>
#include <math.h>

// ---------------- problem constants ----------------
#define BATCH_MAX 65536
#define DIMV 64
#define CTXD 384
#define HIDD 128
#define NPR 5
#define MEMN 10
#define EPSV 1e-8f
#define GRID_A 148
#define GRID_B 148

// ---------------- device scratch ----------------
__device__ float g_ctx[BATCH_MAX * DIMV];
__device__ float g_e[BATCH_MAX * DIMV];
__device__ float g_partials[GRID_A];
__device__ float g_stress;
__device__ float g_gic[2][192];

// ================= kernel A1: ctx = context @ ctx_w^T + b =================
// smem: W [384][64] = 24576 ; X [64][388] = 24832 ; bias 64
#define A1_W   0
#define A1_X   24576
#define A1_B   (24576 + 24832)
#define A1_TOT (A1_B + 64)
#define SMEM_A1 (A1_TOT * 4)

extern "C" __global__ void __launch_bounds__(256)
kA1(const float* __restrict__ context, const float* __restrict__ ctx_w,
    const float* __restrict__ ctx_b, int ntiles)
{
    extern __shared__ float sm[];
    const int t = threadIdx.x;

    for (int i = t; i < 64 * 384; i += 256) {       // ctx_w[d][k] -> [k][64]+d
        int d = i / 384, k = i % 384;
        sm[A1_W + k * 64 + d] = ctx_w[i];
    }
    if (t < 64) sm[A1_B + t] = ctx_b[t];
    __syncthreads();

    const int rb = t >> 4;          // 0..15 -> rows 4rb..4rb+3
    const int jq = t & 15;

    for (int tile = blockIdx.x; tile < ntiles; tile += gridDim.x) {
        __syncthreads();
        const int row0 = tile * 64;
        // stage context tile [64][384] -> stride 388
        {
            const float4* src = (const float4*)(context + (size_t)row0 * CTXD);
            for (int i = t; i < 64 * 96; i += 256) {
                int r = i / 96, c = i % 96;
                ((float4*)(sm + A1_X + r * 388))[c] = src[i];
            }
        }
        __syncthreads();

        float4 bq = *(const float4*)(sm + A1_B + jq * 4);
        float acc[4][4];
        #pragma unroll
        for (int m = 0; m < 4; m++) { acc[m][0]=bq.x; acc[m][1]=bq.y; acc[m][2]=bq.z; acc[m][3]=bq.w; }

        const int r0 = rb * 4;
        #pragma unroll 2
        for (int k = 0; k < CTXD; k++) {
            float4 w = *(const float4*)(sm + A1_W + k * 64 + jq * 4);
            #pragma unroll
            for (int m = 0; m < 4; m++) {
                float x = sm[A1_X + (r0 + m) * 388 + k];
                acc[m][0] = fmaf(x, w.x, acc[m][0]);
                acc[m][1] = fmaf(x, w.y, acc[m][1]);
                acc[m][2] = fmaf(x, w.z, acc[m][2]);
                acc[m][3] = fmaf(x, w.w, acc[m][3]);
            }
        }
        #pragma unroll
        for (int m = 0; m < 4; m++) {
            float4 o; o.x=acc[m][0]; o.y=acc[m][1]; o.z=acc[m][2]; o.w=acc[m][3];
            *(float4*)(g_ctx + (size_t)(row0 + r0 + m) * DIMV + jq * 4) = o;
        }
    }
}

// ================= kernel A2: emo MLP, ideal, res/om/stress ================
#define A2_W1   0                      // [64][128]
#define A2_W2   8192                   // [128][64]
#define A2_IW   16384                  // 5*128
#define A2_PE   17024                  // 5*64
#define A2_B1   17344                  // 128
#define A2_B2   17472                  // 64
#define A2_IB   17536                  // 8
#define A2_PI   17544                  // 64
#define A2_TH   17608                  // [64][68]
#define A2_CT   21960                  // [64][68]
#define A2_H1   26312                  // [64][132]
#define A2_LG   34760                  // [64][8]
#define A2_RED  35272                  // 256
#define A2_TOT  35528
#define SMEM_A2 (A2_TOT * 4)

extern "C" __global__ void __launch_bounds__(256)
kA2(const float* __restrict__ theta,
    const float* __restrict__ emo_w1, const float* __restrict__ emo_b1,
    const float* __restrict__ emo_w2, const float* __restrict__ emo_b2,
    const float* __restrict__ prime_embeds, const float* __restrict__ ideal_w,
    const float* __restrict__ ideal_b, const float* __restrict__ prev_ideal,
    const float* __restrict__ freq_w, const float* __restrict__ freq_b,
    float* __restrict__ out_res, float* __restrict__ out_om,
    float* __restrict__ out_pw, int ntiles)
{
    extern __shared__ float sm[];
    const int t = threadIdx.x;

    for (int i = t; i < HIDD * 64; i += 256) {      // emo_w1[j][d] -> [d][128]+j
        int j = i / 64, d = i % 64;
        sm[A2_W1 + d * 128 + j] = emo_w1[i];
    }
    for (int i = t; i < 64 * HIDD; i += 256) {      // emo_w2[d][j] -> [j][64]+d
        int d = i / 128, j = i % 128;
        sm[A2_W2 + j * 64 + d] = emo_w2[i];
    }
    for (int i = t; i < 5 * 128; i += 256) sm[A2_IW + i] = ideal_w[i];
    for (int i = t; i < 5 * 64;  i += 256) sm[A2_PE + i] = prime_embeds[i];
    if (t < 128) sm[A2_B1 + t] = emo_b1[t];
    if (t < 64)  sm[A2_B2 + t] = emo_b2[t];
    if (t < 5)   sm[A2_IB + t] = ideal_b[t];
    if (t < 64)  sm[A2_PI + t] = prev_ideal[t];
    __syncthreads();

    const float fw = freq_w[0], fb = freq_b[0];
    const int rb = t >> 4, jq = t & 15;
    const int r0 = rb * 4;
    float st_acc = 0.0f;

    for (int tile = blockIdx.x; tile < ntiles; tile += gridDim.x) {
        __syncthreads();
        const int row0 = tile * 64;
        {
            const float4* th4 = (const float4*)(theta + (size_t)row0 * DIMV);
            const float4* cx4 = (const float4*)(g_ctx + (size_t)row0 * DIMV);
            for (int i = t; i < 64 * 16; i += 256) {
                int r = i / 16, c = i % 16;
                ((float4*)(sm + A2_TH + r * 68))[c] = th4[i];
                ((float4*)(sm + A2_CT + r * 68))[c] = cx4[i];
            }
        }
        __syncthreads();

        // ---- h1 = tanh(theta @ w1^T + b1) : 4 rows x quads {jq*4, 64+jq*4} ----
        {
            float4 b1a = *(const float4*)(sm + A2_B1 + jq * 4);
            float4 b1b = *(const float4*)(sm + A2_B1 + 64 + jq * 4);
            float a1[4][4], a2[4][4];
            #pragma unroll
            for (int m = 0; m < 4; m++) {
                a1[m][0]=b1a.x; a1[m][1]=b1a.y; a1[m][2]=b1a.z; a1[m][3]=b1a.w;
                a2[m][0]=b1b.x; a2[m][1]=b1b.y; a2[m][2]=b1b.z; a2[m][3]=b1b.w;
            }
            #pragma unroll 2
            for (int k = 0; k < DIMV; k++) {
                float4 w1 = *(const float4*)(sm + A2_W1 + k * 128 + jq * 4);
                float4 w2 = *(const float4*)(sm + A2_W1 + k * 128 + 64 + jq * 4);
                #pragma unroll
                for (int m = 0; m < 4; m++) {
                    float x = sm[A2_TH + (r0 + m) * 68 + k];
                    a1[m][0]=fmaf(x,w1.x,a1[m][0]); a1[m][1]=fmaf(x,w1.y,a1[m][1]);
                    a1[m][2]=fmaf(x,w1.z,a1[m][2]); a1[m][3]=fmaf(x,w1.w,a1[m][3]);
                    a2[m][0]=fmaf(x,w2.x,a2[m][0]); a2[m][1]=fmaf(x,w2.y,a2[m][1]);
                    a2[m][2]=fmaf(x,w2.z,a2[m][2]); a2[m][3]=fmaf(x,w2.w,a2[m][3]);
                }
            }
            #pragma unroll
            for (int m = 0; m < 4; m++) {
                float* h1 = sm + A2_H1 + (r0 + m) * 132;
                #pragma unroll
                for (int e = 0; e < 4; e++) {
                    h1[jq * 4 + e]      = tanhf(a1[m][e]);
                    h1[64 + jq * 4 + e] = tanhf(a2[m][e]);
                }
            }
        }

        // ---- ideal logits : row = t&63, prime group t>>6 ----
        {
            int row = t & 63, pg = t >> 6;
            const float* thr = sm + A2_TH + row * 68;
            const float* ctr = sm + A2_CT + row * 68;
            for (int pp = 0; pp < 2; pp++) {
                int p = (pp == 0) ? pg : 4;
                if (pp == 1 && pg != 0) break;
                const float* w = sm + A2_IW + p * 128;
                float l = sm[A2_IB + p];
                #pragma unroll 8
                for (int k = 0; k < 64; k++) l = fmaf(thr[k], w[k], l);
                #pragma unroll 8
                for (int k = 0; k < 64; k++) l = fmaf(ctr[k], w[64 + k], l);
                sm[A2_LG + row * 8 + p] = l;
            }
        }
        __syncthreads();

        // ---- emotion output e = relu(h1 @ w2^T + b2) ----
        {
            float4 b2q = *(const float4*)(sm + A2_B2 + jq * 4);
            float ea[4][4];
            #pragma unroll
            for (int m = 0; m < 4; m++) { ea[m][0]=b2q.x; ea[m][1]=b2q.y; ea[m][2]=b2q.z; ea[m][3]=b2q.w; }
            #pragma unroll 2
            for (int k = 0; k < HIDD; k++) {
                float4 w = *(const float4*)(sm + A2_W2 + k * 64 + jq * 4);
                #pragma unroll
                for (int m = 0; m < 4; m++) {
                    float x = sm[A2_H1 + (r0 + m) * 132 + k];
                    ea[m][0]=fmaf(x,w.x,ea[m][0]); ea[m][1]=fmaf(x,w.y,ea[m][1]);
                    ea[m][2]=fmaf(x,w.z,ea[m][2]); ea[m][3]=fmaf(x,w.w,ea[m][3]);
                }
            }
            #pragma unroll
            for (int m = 0; m < 4; m++) {
                float4 ev;
                ev.x=fmaxf(ea[m][0],0.f); ev.y=fmaxf(ea[m][1],0.f);
                ev.z=fmaxf(ea[m][2],0.f); ev.w=fmaxf(ea[m][3],0.f);
                *(float4*)(g_e + (size_t)(row0 + r0 + m) * DIMV + jq * 4) = ev;
            }
        }

        // ---- softmax / theta_ideal / reductions per row ----
        float pi4[4]; { float4 p = *(const float4*)(sm + A2_PI + jq * 4); pi4[0]=p.x; pi4[1]=p.y; pi4[2]=p.z; pi4[3]=p.w; }
        #pragma unroll
        for (int m = 0; m < 4; m++) {
            const int row = r0 + m;
            float l[NPR], mx = -1e30f, pw[NPR];
            #pragma unroll
            for (int p = 0; p < NPR; p++) { l[p] = sm[A2_LG + row * 8 + p]; mx = fmaxf(mx, l[p]); }
            float s = 0.f;
            #pragma unroll
            for (int p = 0; p < NPR; p++) { pw[p] = expf(l[p] - mx); s += pw[p]; }
            float inv = 1.0f / s;
            #pragma unroll
            for (int p = 0; p < NPR; p++) pw[p] *= inv;
            if (jq < NPR) out_pw[(size_t)(row0 + row) * NPR + jq] = pw[jq];

            float4 thq = *(const float4*)(sm + A2_TH + row * 68 + jq * 4);
            float tv[4] = { thq.x, thq.y, thq.z, thq.w };
            float th2 = 0, ti2 = 0, dot = 0, st = 0, fr = 0;
            #pragma unroll
            for (int e = 0; e < 4; e++) {
                int d = jq * 4 + e;
                float iv = 0.f;
                #pragma unroll
                for (int p = 0; p < NPR; p++) iv = fmaf(pw[p], sm[A2_PE + p * 64 + d], iv);
                th2 = fmaf(tv[e], tv[e], th2);
                ti2 = fmaf(iv, iv, ti2);
                dot = fmaf(tv[e], iv, dot);
                float dd = tv[e] - iv; st = fmaf(dd, dd, st);
                float df = iv - pi4[e]; fr = fmaf(df, df, fr);
            }
            st_acc += st;
            #pragma unroll
            for (int o = 1; o < 16; o <<= 1) {
                th2 += __shfl_xor_sync(0xffffffffu, th2, o);
                ti2 += __shfl_xor_sync(0xffffffffu, ti2, o);
                dot += __shfl_xor_sync(0xffffffffu, dot, o);
                fr  += __shfl_xor_sync(0xffffffffu, fr,  o);
            }
            if (jq == 0) {
                float na = sqrtf(th2), nb = sqrtf(ti2);
                float t1 = dot / ((na + EPSV) * (nb + EPSV));
                float den = fmaxf((na / (na + EPSV)) * (nb / (nb + EPSV)), EPSV);
                out_res[row0 + row] = t1 / den;
                float fq = sqrtf(fr);
                out_om[row0 + row] = tanhf(fmaf(fq, fw, fb)) * (1.0f + 0.1f * sinf(fq));
            }
        }
    }

    __syncthreads();
    sm[A2_RED + t] = st_acc;
    __syncthreads();
    for (int o = 128; o > 0; o >>= 1) {
        if (t < o) sm[A2_RED + t] += sm[A2_RED + t + o];
        __syncthreads();
    }
    if (t == 0) g_partials[blockIdx.x] = sm[A2_RED];
}

// ================= kernel C: stress, o_vec, folded gi constants ============
extern "C" __global__ void
kC(const float* __restrict__ tw, const float* __restrict__ memory,
   const float* __restrict__ ipw, const float* __restrict__ ipb,
   const float* __restrict__ outw, const float* __restrict__ outb,
   const float* __restrict__ wih_f, const float* __restrict__ bih_f,
   const float* __restrict__ wih_r, const float* __restrict__ bih_r)
{
    __shared__ float attn[MEMN], mt[DIMV], vv[DIMV], ov[DIMV], stress_s;
    const int t = threadIdx.x;
    if (t == 0) {
        float m = -1e30f;
        for (int i = 0; i < MEMN; i++) m = fmaxf(m, tw[i]);
        float s = 0, ex[MEMN];
        for (int i = 0; i < MEMN; i++) { ex[i] = expf(tw[i] - m); s += ex[i]; }
        for (int i = 0; i < MEMN; i++) attn[i] = ex[i] / s;
        float acc = 0;
        for (int i = 0; i < GRID_A; i++) acc += g_partials[i];
        g_stress = acc; stress_s = acc;
    }
    __syncthreads();
    if (t < DIMV) {
        float s = 0;
        for (int m = 0; m < MEMN; m++) s = fmaf(attn[m], memory[m * DIMV + t], s);
        mt[t] = s;
    }
    __syncthreads();
    if (t < DIMV) {
        float s = ipb[2 * DIMV + t];
        for (int d = 0; d < DIMV; d++) s = fmaf(mt[d], ipw[(2 * DIMV + t) * DIMV + d], s);
        vv[t] = s;
    }
    __syncthreads();
    if (t < DIMV) {
        float s = outb[t];
        for (int i = 0; i < DIMV; i++) s = fmaf(vv[i], outw[t * DIMV + i], s);
        ov[t] = s;
    }
    __syncthreads();
    if (t < 192) {
        float sc = 0.001f * stress_s;
        float gf = bih_f[t], gr = bih_r[t];
        for (int k = 0; k < DIMV; k++) {
            gf = fmaf(ov[k], wih_f[t * 130 + k], gf);
            gr = fmaf(ov[k], wih_r[t * 130 + k], gr);
        }
        float sf = 0, sr = 0;
        for (int k = 64; k < 128; k++) { sf += wih_f[t * 130 + k]; sr += wih_r[t * 130 + k]; }
        g_gic[0][t] = fmaf(sc, sf, gf);
        g_gic[1][t] = fmaf(sc, sr, gr);
    }
}

// ================= kernel B: both GRU directions, 64-row tiles =============
#define B_SWI  0                        // [66][192]
#define B_SWH  12672                    // [64][192]
#define B_SGA  24960                    // 192  (accumulator init: gic+bhh / gic)
#define B_SGH  25152                    // 64   (bhh n-gate)
#define B_SX   25216                    // [64][68]
#define B_SH   29568                    // [64][68]
#define B_TOT  33920
#define SMEM_B (B_TOT * 4)

extern "C" __global__ void __launch_bounds__(256)
kB(const float* __restrict__ wih_f, const float* __restrict__ whh_f,
   const float* __restrict__ bhh_f,
   const float* __restrict__ wih_r, const float* __restrict__ whh_r,
   const float* __restrict__ bhh_r,
   const float* __restrict__ hprev, const float* __restrict__ theta,
   const float* __restrict__ res_in, const float* __restrict__ om_in,
   float* __restrict__ hout, float* __restrict__ thout,
   float* __restrict__ eout, int ntiles, int Btot)
{
    extern __shared__ float sm[];
    const int t = threadIdx.x;
    const int dir = blockIdx.x & 1;

    const float* wih = dir ? wih_r : wih_f;
    const float* whh = dir ? whh_r : whh_f;
    const float* bhh = dir ? bhh_r : bhh_f;
    const float* hp  = hprev + (size_t)dir * Btot * DIMV;
    float* ho        = hout  + (size_t)dir * Btot * DIMV;

    for (int i = t; i < 192 * 66; i += 256) {
        int j = i / 66, c = i % 66;
        sm[B_SWI + c * 192 + j] = wih[j * 130 + 64 + c];
    }
    for (int i = t; i < 192 * 64; i += 256) {
        int j = i / 64, c = i % 64;
        sm[B_SWH + c * 192 + j] = whh[j * 64 + c];
    }
    if (t < 192) {
        float v = g_gic[dir][t];
        if (t < 128) v += bhh[t];
        sm[B_SGA + t] = v;
    }
    if (t < 64) sm[B_SGH + t] = bhh[128 + t];
    __syncthreads();

    const float sc = 0.001f * g_stress;
    const int rb = t >> 4, jq = t & 15;
    const int r0 = rb * 4;
    const float lam = 0.7f, oml = 0.3f;
    const int nblk = gridDim.x >> 1;

    for (int tile = blockIdx.x >> 1; tile < ntiles; tile += nblk) {
        __syncthreads();
        const int row0 = tile * 64;
        {
            const float4* e4 = (const float4*)(g_e + (size_t)row0 * DIMV);
            const float4* h4 = (const float4*)(hp  + (size_t)row0 * DIMV);
            for (int i = t; i < 64 * 16; i += 256) {
                int r = i / 16, c = i % 16;
                ((float4*)(sm + B_SX + r * 68))[c] = e4[i];
                ((float4*)(sm + B_SH + r * 68))[c] = h4[i];
            }
            if (t < 64) {
                sm[B_SX + t * 68 + 64] = res_in[row0 + t];
                sm[B_SX + t * 68 + 65] = om_in[row0 + t];
            }
        }
        __syncthreads();

        float ar[4][4], az[4][4], ain[4][4], ahn[4][4];
        {
            float4 ia = *(const float4*)(sm + B_SGA + jq * 4);
            float4 iz = *(const float4*)(sm + B_SGA + 64 + jq * 4);
            float4 in_ = *(const float4*)(sm + B_SGA + 128 + jq * 4);
            float4 ih = *(const float4*)(sm + B_SGH + jq * 4);
            #pragma unroll
            for (int m = 0; m < 4; m++) {
                ar[m][0]=ia.x; ar[m][1]=ia.y; ar[m][2]=ia.z; ar[m][3]=ia.w;
                az[m][0]=iz.x; az[m][1]=iz.y; az[m][2]=iz.z; az[m][3]=iz.w;
                ain[m][0]=in_.x; ain[m][1]=in_.y; ain[m][2]=in_.z; ain[m][3]=in_.w;
                ahn[m][0]=ih.x; ahn[m][1]=ih.y; ahn[m][2]=ih.z; ahn[m][3]=ih.w;
            }
        }

        for (int k = 0; k < 64; k++) {
            float4 wi0 = *(const float4*)(sm + B_SWI + k * 192 + jq * 4);
            float4 wi1 = *(const float4*)(sm + B_SWI + k * 192 + 64 + jq * 4);
            float4 wi2 = *(const float4*)(sm + B_SWI + k * 192 + 128 + jq * 4);
            float4 wh0 = *(const float4*)(sm + B_SWH + k * 192 + jq * 4);
            float4 wh1 = *(const float4*)(sm + B_SWH + k * 192 + 64 + jq * 4);
            float4 wh2 = *(const float4*)(sm + B_SWH + k * 192 + 128 + jq * 4);
            #pragma unroll
            for (int m = 0; m < 4; m++) {
                float x = sm[B_SX + (r0 + m) * 68 + k];
                float h = sm[B_SH + (r0 + m) * 68 + k];
                ar[m][0]=fmaf(x,wi0.x,ar[m][0]); ar[m][1]=fmaf(x,wi0.y,ar[m][1]);
                ar[m][2]=fmaf(x,wi0.z,ar[m][2]); ar[m][3]=fmaf(x,wi0.w,ar[m][3]);
                ar[m][0]=fmaf(h,wh0.x,ar[m][0]); ar[m][1]=fmaf(h,wh0.y,ar[m][1]);
                ar[m][2]=fmaf(h,wh0.z,ar[m][2]); ar[m][3]=fmaf(h,wh0.w,ar[m][3]);
                az[m][0]=fmaf(x,wi1.x,az[m][0]); az[m][1]=fmaf(x,wi1.y,az[m][1]);
                az[m][2]=fmaf(x,wi1.z,az[m][2]); az[m][3]=fmaf(x,wi1.w,az[m][3]);
                az[m][0]=fmaf(h,wh1.x,az[m][0]); az[m][1]=fmaf(h,wh1.y,az[m][1]);
                az[m][2]=fmaf(h,wh1.z,az[m][2]); az[m][3]=fmaf(h,wh1.w,az[m][3]);
                ain[m][0]=fmaf(x,wi2.x,ain[m][0]); ain[m][1]=fmaf(x,wi2.y,ain[m][1]);
                ain[m][2]=fmaf(x,wi2.z,ain[m][2]); ain[m][3]=fmaf(x,wi2.w,ain[m][3]);
                ahn[m][0]=fmaf(h,wh2.x,ahn[m][0]); ahn[m][1]=fmaf(h,wh2.y,ahn[m][1]);
                ahn[m][2]=fmaf(h,wh2.z,ahn[m][2]); ahn[m][3]=fmaf(h,wh2.w,ahn[m][3]);
            }
        }
        #pragma unroll
        for (int k = 64; k < 66; k++) {
            float4 wi0 = *(const float4*)(sm + B_SWI + k * 192 + jq * 4);
            float4 wi1 = *(const float4*)(sm + B_SWI + k * 192 + 64 + jq * 4);
            float4 wi2 = *(const float4*)(sm + B_SWI + k * 192 + 128 + jq * 4);
            #pragma unroll
            for (int m = 0; m < 4; m++) {
                float x = sm[B_SX + (r0 + m) * 68 + k];
                ar[m][0]=fmaf(x,wi0.x,ar[m][0]); ar[m][1]=fmaf(x,wi0.y,ar[m][1]);
                ar[m][2]=fmaf(x,wi0.z,ar[m][2]); ar[m][3]=fmaf(x,wi0.w,ar[m][3]);
                az[m][0]=fmaf(x,wi1.x,az[m][0]); az[m][1]=fmaf(x,wi1.y,az[m][1]);
                az[m][2]=fmaf(x,wi1.z,az[m][2]); az[m][3]=fmaf(x,wi1.w,az[m][3]);
                ain[m][0]=fmaf(x,wi2.x,ain[m][0]); ain[m][1]=fmaf(x,wi2.y,ain[m][1]);
                ain[m][2]=fmaf(x,wi2.z,ain[m][2]); ain[m][3]=fmaf(x,wi2.w,ain[m][3]);
            }
        }

        #pragma unroll
        for (int m = 0; m < 4; m++) {
            const int row = row0 + r0 + m;
            float4 hn4; float* hn = (float*)&hn4;
            #pragma unroll
            for (int e = 0; e < 4; e++) {
                float rg = 1.0f / (1.0f + expf(-ar[m][e]));
                float zg = 1.0f / (1.0f + expf(-az[m][e]));
                float ng = tanhf(fmaf(rg, ahn[m][e], ain[m][e]));
                float hv = sm[B_SH + (r0 + m) * 68 + jq * 4 + e];
                hn[e] = fmaf(zg, hv - ng, ng);
            }
            const size_t ob = (size_t)row * DIMV + jq * 4;
            *(float4*)(ho + ob) = hn4;
            if (dir == 0) {
                float4 th = *(const float4*)(theta + ob);
                float4 tn;
                tn.x = fmaf(lam, hn4.x, oml * th.x); tn.y = fmaf(lam, hn4.y, oml * th.y);
                tn.z = fmaf(lam, hn4.z, oml * th.z); tn.w = fmaf(lam, hn4.w, oml * th.w);
                *(float4*)(thout + ob) = tn;
                float4 ev = *(const float4*)(sm + B_SX + (r0 + m) * 68 + jq * 4);
                ev.x += sc; ev.y += sc; ev.z += sc; ev.w += sc;
                *(float4*)(eout + ob) = ev;
            }
        }
    }
}

// ================= launch =================
extern "C" void kernel_launch(void* const* d_in, const int* in_sizes, int n_in,
                              void* d_out, int out_size)
{
    const float* theta     = (const float*)d_in[0];
    const float* context   = (const float*)d_in[1];
    const float* h_prev    = (const float*)d_in[2];
    const float* memory    = (const float*)d_in[3];
    const float* tw        = (const float*)d_in[4];
    const float* ipw       = (const float*)d_in[5];
    const float* ipb       = (const float*)d_in[6];
    const float* outw      = (const float*)d_in[7];
    const float* outb      = (const float*)d_in[8];
    const float* emo_w1    = (const float*)d_in[9];
    const float* emo_b1    = (const float*)d_in[10];
    const float* emo_w2    = (const float*)d_in[11];
    const float* emo_b2    = (const float*)d_in[12];
    const float* prime_emb = (const float*)d_in[13];
    const float* ctx_w     = (const float*)d_in[14];
    const float* ctx_b     = (const float*)d_in[15];
    const float* ideal_w   = (const float*)d_in[16];
    const float* ideal_b   = (const float*)d_in[17];
    const float* wih_f     = (const float*)d_in[18];
    const float* whh_f     = (const float*)d_in[19];
    const float* bih_f     = (const float*)d_in[20];
    const float* bhh_f     = (const float*)d_in[21];
    const float* wih_r     = (const float*)d_in[22];
    const float* whh_r     = (const float*)d_in[23];
    const float* bih_r     = (const float*)d_in[24];
    const float* bhh_r     = (const float*)d_in[25];
    const float* freq_w    = (const float*)d_in[26];
    const float* freq_b    = (const float*)d_in[27];
    const float* prev_id   = (const float*)d_in[28];

    const int B = in_sizes[0] / DIMV;
    const int ntiles = B / 64;

    float* out = (float*)d_out;
    float* o_thn = out;
    float* o_h   = out + (size_t)B * DIMV;
    float* o_e   = out + (size_t)3 * B * DIMV;
    float* o_res = out + (size_t)4 * B * DIMV;
    float* o_om  = o_res + B;
    float* o_pw  = o_om + B;

    cudaFuncSetAttribute((const void*)kA1, cudaFuncAttributeMaxDynamicSharedMemorySize, SMEM_A1);
    cudaFuncSetAttribute((const void*)kA2, cudaFuncAttributeMaxDynamicSharedMemorySize, SMEM_A2);
    cudaFuncSetAttribute((const void*)kB,  cudaFuncAttributeMaxDynamicSharedMemorySize, SMEM_B);

    kA1<<<GRID_A, 256, SMEM_A1>>>(context, ctx_w, ctx_b, ntiles);
    kA2<<<GRID_A, 256, SMEM_A2>>>(theta, emo_w1, emo_b1, emo_w2, emo_b2,
                                  prime_emb, ideal_w, ideal_b, prev_id,
                                  freq_w, freq_b, o_res, o_om, o_pw, ntiles);
    kC<<<1, 192>>>(tw, memory, ipw, ipb, outw, outb, wih_f, bih_f, wih_r, bih_r);
    kB<<<GRID_B * 2, 256, SMEM_B>>>(wih_f, whh_f, bhh_f, wih_r, whh_r, bhh_r,
                                    h_prev, theta, o_res, o_om,
                                    o_h, o_thn, o_e, ntiles, B);
}

// round 6
// speedup vs baseline: 2.5991x; 1.4341x over previous
#include <cuda_runtime.h>
#include <math.h>

// ---------------- problem constants ----------------
#define BATCH_MAX 65536
#define DIMV 64
#define CTXD 384
#define HIDD 128
#define NPR 5
#define MEMN 10
#define EPSV 1e-8f
#define GRID_A 148
#define EPS 1e-8f

typedef unsigned long long u64;

__device__ __forceinline__ u64 pk2(float a) {
    u64 r; asm("mov.b64 %0,{%1,%1};" : "=l"(r) : "f"(a)); return r;
}
__device__ __forceinline__ void ffma2(u64& d, u64 a, u64 b) {
    asm("fma.rn.f32x2 %0,%1,%2,%0;" : "+l"(d) : "l"(a), "l"(b));
}
__device__ __forceinline__ float2 up2(u64 v) {
    float2 f; asm("mov.b64 {%0,%1},%2;" : "=f"(f.x), "=f"(f.y) : "l"(v)); return f;
}

// ---------------- device scratch ----------------
__device__ float g_e[BATCH_MAX * DIMV];
__device__ float g_partials[GRID_A];
__device__ float g_stress;
__device__ float g_gic[2][192];
__device__ float g_M[NPR * CTXD];
__device__ float g_ibc[NPR];

// ================= kernel C0: M = ideal_w[:,64:] @ ctx_w, ibc ==============
extern "C" __global__ void
kC0(const float* __restrict__ ideal_w, const float* __restrict__ ctx_w,
    const float* __restrict__ ctx_b, const float* __restrict__ ideal_b)
{
    const int p = blockIdx.x;        // 0..4
    const int k = threadIdx.x;       // 0..383
    float s = 0.0f;
    #pragma unroll 8
    for (int d = 0; d < 64; d++)
        s = fmaf(ideal_w[p * 128 + 64 + d], ctx_w[d * 384 + k], s);
    g_M[p * 384 + k] = s;
    if (k == 0) {
        float c = ideal_b[p];
        for (int d = 0; d < 64; d++)
            c = fmaf(ideal_w[p * 128 + 64 + d], ctx_b[d], c);
        g_ibc[p] = c;
    }
}

// ================= kernel A2: emo MLP, ideal logits, res/om/stress =========
#define A2_W1   0                      // [64][128]
#define A2_W2   8192                   // [128][64]
#define A2_IWT  16384                  // 5*64 (theta half of ideal_w)
#define A2_M    16704                  // 5*384
#define A2_PE   18624                  // 5*64
#define A2_B1   18944                  // 128
#define A2_B2   19072                  // 64
#define A2_IBC  19136                  // 8
#define A2_PI   19144                  // 64
#define A2_TH   19208                  // [128][68]
#define A2_H1   27912                  // [128][132]
#define A2_LG   44808                  // [128][8]
#define A2_RED  45832                  // 512
#define A2_TOT  46344
#define SMEM_A2 (A2_TOT * 4)

extern "C" __global__ void __launch_bounds__(512)
kA2(const float* __restrict__ theta, const float* __restrict__ context,
    const float* __restrict__ emo_w1, const float* __restrict__ emo_b1,
    const float* __restrict__ emo_w2, const float* __restrict__ emo_b2,
    const float* __restrict__ prime_embeds, const float* __restrict__ ideal_w,
    const float* __restrict__ prev_ideal,
    const float* __restrict__ freq_w, const float* __restrict__ freq_b,
    float* __restrict__ out_res, float* __restrict__ out_om,
    float* __restrict__ out_pw, int ntiles)
{
    extern __shared__ float sm[];
    const int t = threadIdx.x;

    for (int i = t; i < HIDD * 64; i += 512) {      // emo_w1[j][d] -> [d][128]+j
        int j = i / 64, d = i % 64;
        sm[A2_W1 + d * 128 + j] = emo_w1[i];
    }
    for (int i = t; i < 64 * HIDD; i += 512) {      // emo_w2[d][j] -> [j][64]+d
        int d = i / 128, j = i % 128;
        sm[A2_W2 + j * 64 + d] = emo_w2[i];
    }
    for (int i = t; i < NPR * 64; i += 512)         // theta half of ideal_w
        sm[A2_IWT + i] = ideal_w[(i / 64) * 128 + (i % 64)];
    for (int i = t; i < NPR * CTXD; i += 512) sm[A2_M + i] = g_M[i];
    for (int i = t; i < NPR * 64;  i += 512) sm[A2_PE + i] = prime_embeds[i];
    if (t < 128) sm[A2_B1 + t] = emo_b1[t];
    if (t < 64)  sm[A2_B2 + t] = emo_b2[t];
    if (t < NPR) sm[A2_IBC + t] = g_ibc[t];
    if (t < 64)  sm[A2_PI + t] = prev_ideal[t];
    __syncthreads();

    const float fw = freq_w[0], fb = freq_b[0];
    const int rb = t >> 4, jq = t & 15;             // rb 0..31
    const int r0 = rb * 4;
    const int lane = t & 31, wp = t >> 5;           // wp 0..15
    float st_acc = 0.0f;

    for (int tile = blockIdx.x; tile < ntiles; tile += gridDim.x) {
        __syncthreads();
        const int row0 = tile * 128;
        {
            const float4* th4 = (const float4*)(theta + (size_t)row0 * DIMV);
            for (int i = t; i < 128 * 16; i += 512) {
                int r = i / 16, c = i % 16;
                ((float4*)(sm + A2_TH + r * 68))[c] = th4[i];
            }
        }
        __syncthreads();

        // ---- h1 = tanh(theta @ w1^T + b1), f32x2 packed ----
        {
            ulonglong2 b1a = *(const ulonglong2*)(sm + A2_B1 + jq * 4);
            ulonglong2 b1b = *(const ulonglong2*)(sm + A2_B1 + 64 + jq * 4);
            u64 a1[4][2], a2[4][2];
            #pragma unroll
            for (int m = 0; m < 4; m++) {
                a1[m][0] = b1a.x; a1[m][1] = b1a.y;
                a2[m][0] = b1b.x; a2[m][1] = b1b.y;
            }
            #pragma unroll 2
            for (int k = 0; k < DIMV; k++) {
                ulonglong2 w1 = *(const ulonglong2*)(sm + A2_W1 + k * 128 + jq * 4);
                ulonglong2 w2 = *(const ulonglong2*)(sm + A2_W1 + k * 128 + 64 + jq * 4);
                #pragma unroll
                for (int m = 0; m < 4; m++) {
                    u64 xx = pk2(sm[A2_TH + (r0 + m) * 68 + k]);
                    ffma2(a1[m][0], xx, w1.x); ffma2(a1[m][1], xx, w1.y);
                    ffma2(a2[m][0], xx, w2.x); ffma2(a2[m][1], xx, w2.y);
                }
            }
            #pragma unroll
            for (int m = 0; m < 4; m++) {
                float* h1 = sm + A2_H1 + (r0 + m) * 132;
                float2 v0 = up2(a1[m][0]), v1 = up2(a1[m][1]);
                float2 v2 = up2(a2[m][0]), v3 = up2(a2[m][1]);
                h1[jq * 4 + 0] = tanhf(v0.x); h1[jq * 4 + 1] = tanhf(v0.y);
                h1[jq * 4 + 2] = tanhf(v1.x); h1[jq * 4 + 3] = tanhf(v1.y);
                h1[64 + jq * 4 + 0] = tanhf(v2.x); h1[64 + jq * 4 + 1] = tanhf(v2.y);
                h1[64 + jq * 4 + 2] = tanhf(v3.x); h1[64 + jq * 4 + 3] = tanhf(v3.y);
            }
        }

        // ---- ideal logits: warp wp handles rows wp*8..wp*8+7 ----
        for (int rr = 0; rr < 8; rr++) {
            const int row = wp * 8 + rr;
            const float* crow = context + (size_t)(row0 + row) * CTXD;
            float p0 = 0, p1 = 0, p2 = 0, p3 = 0, p4 = 0;
            #pragma unroll
            for (int ch = 0; ch < 12; ch++) {
                int k = lane + 32 * ch;
                float c = __ldg(crow + k);
                p0 = fmaf(c, sm[A2_M + 0 * 384 + k], p0);
                p1 = fmaf(c, sm[A2_M + 1 * 384 + k], p1);
                p2 = fmaf(c, sm[A2_M + 2 * 384 + k], p2);
                p3 = fmaf(c, sm[A2_M + 3 * 384 + k], p3);
                p4 = fmaf(c, sm[A2_M + 4 * 384 + k], p4);
            }
            #pragma unroll
            for (int ch = 0; ch < 2; ch++) {
                int k = lane + 32 * ch;
                float tv = sm[A2_TH + row * 68 + k];
                p0 = fmaf(tv, sm[A2_IWT + 0 * 64 + k], p0);
                p1 = fmaf(tv, sm[A2_IWT + 1 * 64 + k], p1);
                p2 = fmaf(tv, sm[A2_IWT + 2 * 64 + k], p2);
                p3 = fmaf(tv, sm[A2_IWT + 3 * 64 + k], p3);
                p4 = fmaf(tv, sm[A2_IWT + 4 * 64 + k], p4);
            }
            #pragma unroll
            for (int o = 16; o > 0; o >>= 1) {
                p0 += __shfl_xor_sync(0xffffffffu, p0, o);
                p1 += __shfl_xor_sync(0xffffffffu, p1, o);
                p2 += __shfl_xor_sync(0xffffffffu, p2, o);
                p3 += __shfl_xor_sync(0xffffffffu, p3, o);
                p4 += __shfl_xor_sync(0xffffffffu, p4, o);
            }
            if (lane == 0) {
                sm[A2_LG + row * 8 + 0] = p0 + sm[A2_IBC + 0];
                sm[A2_LG + row * 8 + 1] = p1 + sm[A2_IBC + 1];
                sm[A2_LG + row * 8 + 2] = p2 + sm[A2_IBC + 2];
                sm[A2_LG + row * 8 + 3] = p3 + sm[A2_IBC + 3];
                sm[A2_LG + row * 8 + 4] = p4 + sm[A2_IBC + 4];
            }
        }
        __syncthreads();

        // ---- e = relu(h1 @ w2^T + b2), f32x2 packed ----
        {
            ulonglong2 b2q = *(const ulonglong2*)(sm + A2_B2 + jq * 4);
            u64 ea[4][2];
            #pragma unroll
            for (int m = 0; m < 4; m++) { ea[m][0] = b2q.x; ea[m][1] = b2q.y; }
            #pragma unroll 2
            for (int k = 0; k < HIDD; k++) {
                ulonglong2 w = *(const ulonglong2*)(sm + A2_W2 + k * 64 + jq * 4);
                #pragma unroll
                for (int m = 0; m < 4; m++) {
                    u64 xx = pk2(sm[A2_H1 + (r0 + m) * 132 + k]);
                    ffma2(ea[m][0], xx, w.x); ffma2(ea[m][1], xx, w.y);
                }
            }
            #pragma unroll
            for (int m = 0; m < 4; m++) {
                float2 v0 = up2(ea[m][0]), v1 = up2(ea[m][1]);
                float4 ev;
                ev.x = fmaxf(v0.x, 0.f); ev.y = fmaxf(v0.y, 0.f);
                ev.z = fmaxf(v1.x, 0.f); ev.w = fmaxf(v1.y, 0.f);
                *(float4*)(g_e + (size_t)(row0 + r0 + m) * DIMV + jq * 4) = ev;
            }
        }

        // ---- softmax / theta_ideal / reductions ----
        float pi4[4];
        { float4 p = *(const float4*)(sm + A2_PI + jq * 4); pi4[0]=p.x; pi4[1]=p.y; pi4[2]=p.z; pi4[3]=p.w; }
        #pragma unroll
        for (int m = 0; m < 4; m++) {
            const int row = r0 + m;
            float l[NPR], mx = -1e30f, pw[NPR];
            #pragma unroll
            for (int p = 0; p < NPR; p++) { l[p] = sm[A2_LG + row * 8 + p]; mx = fmaxf(mx, l[p]); }
            float s = 0.f;
            #pragma unroll
            for (int p = 0; p < NPR; p++) { pw[p] = expf(l[p] - mx); s += pw[p]; }
            float inv = 1.0f / s;
            #pragma unroll
            for (int p = 0; p < NPR; p++) pw[p] *= inv;
            if (jq < NPR) out_pw[(size_t)(row0 + row) * NPR + jq] = pw[jq];

            float4 thq = *(const float4*)(sm + A2_TH + row * 68 + jq * 4);
            float tv[4] = { thq.x, thq.y, thq.z, thq.w };
            float th2 = 0, ti2 = 0, dot = 0, st = 0, fr = 0;
            #pragma unroll
            for (int e = 0; e < 4; e++) {
                int d = jq * 4 + e;
                float iv = 0.f;
                #pragma unroll
                for (int p = 0; p < NPR; p++) iv = fmaf(pw[p], sm[A2_PE + p * 64 + d], iv);
                th2 = fmaf(tv[e], tv[e], th2);
                ti2 = fmaf(iv, iv, ti2);
                dot = fmaf(tv[e], iv, dot);
                float dd = tv[e] - iv; st = fmaf(dd, dd, st);
                float df = iv - pi4[e]; fr = fmaf(df, df, fr);
            }
            st_acc += st;
            #pragma unroll
            for (int o = 1; o < 16; o <<= 1) {
                th2 += __shfl_xor_sync(0xffffffffu, th2, o);
                ti2 += __shfl_xor_sync(0xffffffffu, ti2, o);
                dot += __shfl_xor_sync(0xffffffffu, dot, o);
                fr  += __shfl_xor_sync(0xffffffffu, fr,  o);
            }
            if (jq == 0) {
                float na = sqrtf(th2), nb = sqrtf(ti2);
                float t1 = dot / ((na + EPSV) * (nb + EPSV));
                float den = fmaxf((na / (na + EPSV)) * (nb / (nb + EPSV)), EPSV);
                out_res[row0 + row] = t1 / den;
                float fq = sqrtf(fr);
                out_om[row0 + row] = tanhf(fmaf(fq, fw, fb)) * (1.0f + 0.1f * sinf(fq));
            }
        }
    }

    __syncthreads();
    sm[A2_RED + t] = st_acc;
    __syncthreads();
    for (int o = 256; o > 0; o >>= 1) {
        if (t < o) sm[A2_RED + t] += sm[A2_RED + t + o];
        __syncthreads();
    }
    if (t == 0) g_partials[blockIdx.x] = sm[A2_RED];
}

// ================= kernel C: stress, o_vec, folded gi constants ============
extern "C" __global__ void
kC(const float* __restrict__ tw, const float* __restrict__ memory,
   const float* __restrict__ ipw, const float* __restrict__ ipb,
   const float* __restrict__ outw, const float* __restrict__ outb,
   const float* __restrict__ wih_f, const float* __restrict__ bih_f,
   const float* __restrict__ wih_r, const float* __restrict__ bih_r)
{
    __shared__ float attn[MEMN], mt[DIMV], vv[DIMV], ov[DIMV], stress_s;
    const int t = threadIdx.x;
    if (t == 0) {
        float m = -1e30f;
        for (int i = 0; i < MEMN; i++) m = fmaxf(m, tw[i]);
        float s = 0, ex[MEMN];
        for (int i = 0; i < MEMN; i++) { ex[i] = expf(tw[i] - m); s += ex[i]; }
        for (int i = 0; i < MEMN; i++) attn[i] = ex[i] / s;
        float acc = 0;
        for (int i = 0; i < GRID_A; i++) acc += g_partials[i];
        g_stress = acc; stress_s = acc;
    }
    __syncthreads();
    if (t < DIMV) {
        float s = 0;
        for (int m = 0; m < MEMN; m++) s = fmaf(attn[m], memory[m * DIMV + t], s);
        mt[t] = s;
    }
    __syncthreads();
    if (t < DIMV) {
        float s = ipb[2 * DIMV + t];
        for (int d = 0; d < DIMV; d++) s = fmaf(mt[d], ipw[(2 * DIMV + t) * DIMV + d], s);
        vv[t] = s;
    }
    __syncthreads();
    if (t < DIMV) {
        float s = outb[t];
        for (int i = 0; i < DIMV; i++) s = fmaf(vv[i], outw[t * DIMV + i], s);
        ov[t] = s;
    }
    __syncthreads();
    if (t < 192) {
        float sc = 0.001f * stress_s;
        float gf = bih_f[t], gr = bih_r[t];
        for (int k = 0; k < DIMV; k++) {
            gf = fmaf(ov[k], wih_f[t * 130 + k], gf);
            gr = fmaf(ov[k], wih_r[t * 130 + k], gr);
        }
        float sf = 0, sr = 0;
        for (int k = 64; k < 128; k++) { sf += wih_f[t * 130 + k]; sr += wih_r[t * 130 + k]; }
        g_gic[0][t] = fmaf(sc, sf, gf);
        g_gic[1][t] = fmaf(sc, sr, gr);
    }
}

// ================= kernel B: both GRU directions, f32x2, 128-row tiles =====
#define B_SWI  0                        // [66][192]
#define B_SWH  12672                    // [64][192]
#define B_SGA  24960                    // 192
#define B_SGH  25152                    // 64
#define B_SX   25216                    // [128][68]
#define B_SH   33920                    // [128][68]
#define B_TOT  42624
#define SMEM_B (B_TOT * 4)

extern "C" __global__ void __launch_bounds__(512)
kB(const float* __restrict__ wih_f, const float* __restrict__ whh_f,
   const float* __restrict__ bhh_f,
   const float* __restrict__ wih_r, const float* __restrict__ whh_r,
   const float* __restrict__ bhh_r,
   const float* __restrict__ hprev, const float* __restrict__ theta,
   const float* __restrict__ res_in, const float* __restrict__ om_in,
   float* __restrict__ hout, float* __restrict__ thout,
   float* __restrict__ eout, int ntiles, int Btot)
{
    extern __shared__ float sm[];
    const int t = threadIdx.x;
    const int dir = blockIdx.x & 1;

    const float* wih = dir ? wih_r : wih_f;
    const float* whh = dir ? whh_r : whh_f;
    const float* bhh = dir ? bhh_r : bhh_f;
    const float* hp  = hprev + (size_t)dir * Btot * DIMV;
    float* ho        = hout  + (size_t)dir * Btot * DIMV;

    for (int i = t; i < 192 * 66; i += 512) {
        int j = i / 66, c = i % 66;
        sm[B_SWI + c * 192 + j] = wih[j * 130 + 64 + c];
    }
    for (int i = t; i < 192 * 64; i += 512) {
        int j = i / 64, c = i % 64;
        sm[B_SWH + c * 192 + j] = whh[j * 64 + c];
    }
    if (t < 192) {
        float v = g_gic[dir][t];
        if (t < 128) v += bhh[t];
        sm[B_SGA + t] = v;
    }
    if (t < 64) sm[B_SGH + t] = bhh[128 + t];
    __syncthreads();

    const float sc = 0.001f * g_stress;
    const int rb = t >> 4, jq = t & 15;       // rb 0..31
    const int r0 = rb * 4;
    const float lam = 0.7f, oml = 0.3f;
    const int nblk = gridDim.x >> 1;

    for (int tile = blockIdx.x >> 1; tile < ntiles; tile += nblk) {
        __syncthreads();
        const int row0 = tile * 128;
        {
            const float4* e4 = (const float4*)(g_e + (size_t)row0 * DIMV);
            const float4* h4 = (const float4*)(hp  + (size_t)row0 * DIMV);
            for (int i = t; i < 128 * 16; i += 512) {
                int r = i / 16, c = i % 16;
                ((float4*)(sm + B_SX + r * 68))[c] = e4[i];
                ((float4*)(sm + B_SH + r * 68))[c] = h4[i];
            }
            if (t < 128) {
                sm[B_SX + t * 68 + 64] = res_in[row0 + t];
                sm[B_SX + t * 68 + 65] = om_in[row0 + t];
            }
        }
        __syncthreads();

        u64 ar[4][2], az[4][2], an[4][2], ah[4][2];
        {
            ulonglong2 ia = *(const ulonglong2*)(sm + B_SGA + jq * 4);
            ulonglong2 iz = *(const ulonglong2*)(sm + B_SGA + 64 + jq * 4);
            ulonglong2 in_ = *(const ulonglong2*)(sm + B_SGA + 128 + jq * 4);
            ulonglong2 ih = *(const ulonglong2*)(sm + B_SGH + jq * 4);
            #pragma unroll
            for (int m = 0; m < 4; m++) {
                ar[m][0] = ia.x;  ar[m][1] = ia.y;
                az[m][0] = iz.x;  az[m][1] = iz.y;
                an[m][0] = in_.x; an[m][1] = in_.y;
                ah[m][0] = ih.x;  ah[m][1] = ih.y;
            }
        }

        #pragma unroll 1
        for (int k = 0; k < 64; k++) {
            ulonglong2 wr_i = *(const ulonglong2*)(sm + B_SWI + k * 192 + jq * 4);
            ulonglong2 wz_i = *(const ulonglong2*)(sm + B_SWI + k * 192 + 64 + jq * 4);
            ulonglong2 wn_i = *(const ulonglong2*)(sm + B_SWI + k * 192 + 128 + jq * 4);
            ulonglong2 wr_h = *(const ulonglong2*)(sm + B_SWH + k * 192 + jq * 4);
            ulonglong2 wz_h = *(const ulonglong2*)(sm + B_SWH + k * 192 + 64 + jq * 4);
            ulonglong2 wn_h = *(const ulonglong2*)(sm + B_SWH + k * 192 + 128 + jq * 4);
            #pragma unroll
            for (int m = 0; m < 4; m++) {
                u64 xx = pk2(sm[B_SX + (r0 + m) * 68 + k]);
                u64 hh = pk2(sm[B_SH + (r0 + m) * 68 + k]);
                ffma2(ar[m][0], xx, wr_i.x); ffma2(ar[m][1], xx, wr_i.y);
                ffma2(ar[m][0], hh, wr_h.x); ffma2(ar[m][1], hh, wr_h.y);
                ffma2(az[m][0], xx, wz_i.x); ffma2(az[m][1], xx, wz_i.y);
                ffma2(az[m][0], hh, wz_h.x); ffma2(az[m][1], hh, wz_h.y);
                ffma2(an[m][0], xx, wn_i.x); ffma2(an[m][1], xx, wn_i.y);
                ffma2(ah[m][0], hh, wn_h.x); ffma2(ah[m][1], hh, wn_h.y);
            }
        }
        #pragma unroll
        for (int k = 64; k < 66; k++) {
            ulonglong2 wr_i = *(const ulonglong2*)(sm + B_SWI + k * 192 + jq * 4);
            ulonglong2 wz_i = *(const ulonglong2*)(sm + B_SWI + k * 192 + 64 + jq * 4);
            ulonglong2 wn_i = *(const ulonglong2*)(sm + B_SWI + k * 192 + 128 + jq * 4);
            #pragma unroll
            for (int m = 0; m < 4; m++) {
                u64 xx = pk2(sm[B_SX + (r0 + m) * 68 + k]);
                ffma2(ar[m][0], xx, wr_i.x); ffma2(ar[m][1], xx, wr_i.y);
                ffma2(az[m][0], xx, wz_i.x); ffma2(az[m][1], xx, wz_i.y);
                ffma2(an[m][0], xx, wn_i.x); ffma2(an[m][1], xx, wn_i.y);
            }
        }

        #pragma unroll
        for (int m = 0; m < 4; m++) {
            const int row = row0 + r0 + m;
            float rv[4], zv[4], nv[4], hv2[4];
            { float2 a = up2(ar[m][0]), b = up2(ar[m][1]); rv[0]=a.x; rv[1]=a.y; rv[2]=b.x; rv[3]=b.y; }
            { float2 a = up2(az[m][0]), b = up2(az[m][1]); zv[0]=a.x; zv[1]=a.y; zv[2]=b.x; zv[3]=b.y; }
            { float2 a = up2(an[m][0]), b = up2(an[m][1]); nv[0]=a.x; nv[1]=a.y; nv[2]=b.x; nv[3]=b.y; }
            { float2 a = up2(ah[m][0]), b = up2(ah[m][1]); hv2[0]=a.x; hv2[1]=a.y; hv2[2]=b.x; hv2[3]=b.y; }
            float4 hn4; float* hn = (float*)&hn4;
            #pragma unroll
            for (int e = 0; e < 4; e++) {
                float rg = 1.0f / (1.0f + expf(-rv[e]));
                float zg = 1.0f / (1.0f + expf(-zv[e]));
                float ng = tanhf(fmaf(rg, hv2[e], nv[e]));
                float hvp = sm[B_SH + (r0 + m) * 68 + jq * 4 + e];
                hn[e] = fmaf(zg, hvp - ng, ng);
            }
            const size_t ob = (size_t)row * DIMV + jq * 4;
            *(float4*)(ho + ob) = hn4;
            if (dir == 0) {
                float4 th = *(const float4*)(theta + ob);
                float4 tn;
                tn.x = fmaf(lam, hn4.x, oml * th.x); tn.y = fmaf(lam, hn4.y, oml * th.y);
                tn.z = fmaf(lam, hn4.z, oml * th.z); tn.w = fmaf(lam, hn4.w, oml * th.w);
                *(float4*)(thout + ob) = tn;
                float4 ev = *(const float4*)(sm + B_SX + (r0 + m) * 68 + jq * 4);
                ev.x += sc; ev.y += sc; ev.z += sc; ev.w += sc;
                *(float4*)(eout + ob) = ev;
            }
        }
    }
}

// ================= launch =================
extern "C" void kernel_launch(void* const* d_in, const int* in_sizes, int n_in,
                              void* d_out, int out_size)
{
    const float* theta     = (const float*)d_in[0];
    const float* context   = (const float*)d_in[1];
    const float* h_prev    = (const float*)d_in[2];
    const float* memory    = (const float*)d_in[3];
    const float* tw        = (const float*)d_in[4];
    const float* ipw       = (const float*)d_in[5];
    const float* ipb       = (const float*)d_in[6];
    const float* outw      = (const float*)d_in[7];
    const float* outb      = (const float*)d_in[8];
    const float* emo_w1    = (const float*)d_in[9];
    const float* emo_b1    = (const float*)d_in[10];
    const float* emo_w2    = (const float*)d_in[11];
    const float* emo_b2    = (const float*)d_in[12];
    const float* prime_emb = (const float*)d_in[13];
    const float* ctx_w     = (const float*)d_in[14];
    const float* ctx_b     = (const float*)d_in[15];
    const float* ideal_w   = (const float*)d_in[16];
    const float* ideal_b   = (const float*)d_in[17];
    const float* wih_f     = (const float*)d_in[18];
    const float* whh_f     = (const float*)d_in[19];
    const float* bih_f     = (const float*)d_in[20];
    const float* bhh_f     = (const float*)d_in[21];
    const float* wih_r     = (const float*)d_in[22];
    const float* whh_r     = (const float*)d_in[23];
    const float* bih_r     = (const float*)d_in[24];
    const float* bhh_r     = (const float*)d_in[25];
    const float* freq_w    = (const float*)d_in[26];
    const float* freq_b    = (const float*)d_in[27];
    const float* prev_id   = (const float*)d_in[28];

    const int B = in_sizes[0] / DIMV;
    const int ntiles = B / 128;

    float* out = (float*)d_out;
    float* o_thn = out;
    float* o_h   = out + (size_t)B * DIMV;
    float* o_e   = out + (size_t)3 * B * DIMV;
    float* o_res = out + (size_t)4 * B * DIMV;
    float* o_om  = o_res + B;
    float* o_pw  = o_om + B;

    cudaFuncSetAttribute((const void*)kA2, cudaFuncAttributeMaxDynamicSharedMemorySize, SMEM_A2);
    cudaFuncSetAttribute((const void*)kB,  cudaFuncAttributeMaxDynamicSharedMemorySize, SMEM_B);

    kC0<<<NPR, CTXD>>>(ideal_w, ctx_w, ctx_b, ideal_b);
    kA2<<<GRID_A, 512, SMEM_A2>>>(theta, context, emo_w1, emo_b1, emo_w2, emo_b2,
                                  prime_emb, ideal_w, prev_id,
                                  freq_w, freq_b, o_res, o_om, o_pw, ntiles);
    kC<<<1, 192>>>(tw, memory, ipw, ipb, outw, outb, wih_f, bih_f, wih_r, bih_r);
    kB<<<296, 512, SMEM_B>>>(wih_f, whh_f, bhh_f, wih_r, whh_r, bhh_r,
                             h_prev, theta, o_res, o_om,
                             o_h, o_thn, o_e, ntiles, B);
}

// round 7
// speedup vs baseline: 2.7119x; 1.0434x over previous
#include <cuda_runtime.h>
#include <math.h>

// ---------------- problem constants ----------------
#define BATCH_MAX 65536
#define DIMV 64
#define CTXD 384
#define HIDD 128
#define NPR 5
#define MEMN 10
#define EPSV 1e-8f
#define GRID_A 148

typedef unsigned long long u64;

__device__ __forceinline__ u64 pk2(float a) {
    u64 r; asm("mov.b64 %0,{%1,%1};" : "=l"(r) : "f"(a)); return r;
}
__device__ __forceinline__ void ffma2(u64& d, u64 a, u64 b) {
    asm("fma.rn.f32x2 %0,%1,%2,%0;" : "+l"(d) : "l"(a), "l"(b));
}
__device__ __forceinline__ float2 up2(u64 v) {
    float2 f; asm("mov.b64 {%0,%1},%2;" : "=f"(f.x), "=f"(f.y) : "l"(v)); return f;
}

// ---------------- device scratch ----------------
__device__ float g_e[BATCH_MAX * DIMV];
__device__ float g_partials[GRID_A];
__device__ float g_stress;
__device__ float g_gic[2][192];
__device__ float g_M[NPR * CTXD];
__device__ float g_ibc[NPR];

// ================= kernel C0: M = ideal_w[:,64:] @ ctx_w, ibc ==============
extern "C" __global__ void
kC0(const float* __restrict__ ideal_w, const float* __restrict__ ctx_w,
    const float* __restrict__ ctx_b, const float* __restrict__ ideal_b)
{
    const int p = blockIdx.x;        // 0..4
    const int k = threadIdx.x;       // 0..383
    float s = 0.0f;
    #pragma unroll 8
    for (int d = 0; d < 64; d++)
        s = fmaf(ideal_w[p * 128 + 64 + d], ctx_w[d * 384 + k], s);
    g_M[p * 384 + k] = s;
    if (k == 0) {
        float c = ideal_b[p];
        for (int d = 0; d < 64; d++)
            c = fmaf(ideal_w[p * 128 + 64 + d], ctx_b[d], c);
        g_ibc[p] = c;
    }
}

// ================= kernel A2: emo MLP, ideal logits, res/om/stress =========
#define A2_W1   0                      // [64][128]
#define A2_W2   8192                   // [128][64]
#define A2_IWT  16384                  // 5*64
#define A2_M    16704                  // 5*384
#define A2_PE   18624                  // 5*64
#define A2_B1   18944                  // 128
#define A2_B2   19072                  // 64
#define A2_IBC  19136                  // 8
#define A2_PI   19144                  // 64
#define A2_TH   19208                  // [128][68]
#define A2_H1   27912                  // [128][132]
#define A2_LG   44808                  // [128][8]
#define A2_RED  45832                  // 512
#define A2_TOT  46344
#define SMEM_A2 (A2_TOT * 4)

extern "C" __global__ void __launch_bounds__(512)
kA2(const float* __restrict__ theta, const float* __restrict__ context,
    const float* __restrict__ emo_w1, const float* __restrict__ emo_b1,
    const float* __restrict__ emo_w2, const float* __restrict__ emo_b2,
    const float* __restrict__ prime_embeds, const float* __restrict__ ideal_w,
    const float* __restrict__ prev_ideal,
    const float* __restrict__ freq_w, const float* __restrict__ freq_b,
    float* __restrict__ out_res, float* __restrict__ out_om,
    float* __restrict__ out_pw, int ntiles)
{
    extern __shared__ float sm[];
    const int t = threadIdx.x;

    for (int i = t; i < HIDD * 64; i += 512) {      // emo_w1[j][d] -> [d][128]+j
        int j = i / 64, d = i % 64;
        sm[A2_W1 + d * 128 + j] = emo_w1[i];
    }
    for (int i = t; i < 64 * HIDD; i += 512) {      // emo_w2[d][j] -> [j][64]+d
        int d = i / 128, j = i % 128;
        sm[A2_W2 + j * 64 + d] = emo_w2[i];
    }
    for (int i = t; i < NPR * 64; i += 512)
        sm[A2_IWT + i] = ideal_w[(i / 64) * 128 + (i % 64)];
    for (int i = t; i < NPR * CTXD; i += 512) sm[A2_M + i] = g_M[i];
    for (int i = t; i < NPR * 64;  i += 512) sm[A2_PE + i] = prime_embeds[i];
    if (t < 128) sm[A2_B1 + t] = emo_b1[t];
    if (t < 64)  sm[A2_B2 + t] = emo_b2[t];
    if (t < NPR) sm[A2_IBC + t] = g_ibc[t];
    if (t < 64)  sm[A2_PI + t] = prev_ideal[t];
    __syncthreads();

    const float fw = freq_w[0], fb = freq_b[0];
    const int rb = t >> 4, jq = t & 15;
    const int r0 = rb * 4;
    const int lane = t & 31, wp = t >> 5;
    float st_acc = 0.0f;

    for (int tile = blockIdx.x; tile < ntiles; tile += gridDim.x) {
        __syncthreads();
        const int row0 = tile * 128;
        {
            const float4* th4 = (const float4*)(theta + (size_t)row0 * DIMV);
            for (int i = t; i < 128 * 16; i += 512) {
                int r = i / 16, c = i % 16;
                ((float4*)(sm + A2_TH + r * 68))[c] = th4[i];
            }
        }
        __syncthreads();

        // ---- h1 = tanh(theta @ w1^T + b1), f32x2, float4 x over k ----
        {
            ulonglong2 b1a = *(const ulonglong2*)(sm + A2_B1 + jq * 4);
            ulonglong2 b1b = *(const ulonglong2*)(sm + A2_B1 + 64 + jq * 4);
            u64 a1[4][2], a2[4][2];
            #pragma unroll
            for (int m = 0; m < 4; m++) {
                a1[m][0] = b1a.x; a1[m][1] = b1a.y;
                a2[m][0] = b1b.x; a2[m][1] = b1b.y;
            }
            #pragma unroll 1
            for (int k4 = 0; k4 < DIMV; k4 += 4) {
                float4 xv[4];
                #pragma unroll
                for (int m = 0; m < 4; m++)
                    xv[m] = *(const float4*)(sm + A2_TH + (r0 + m) * 68 + k4);
                #pragma unroll
                for (int kk = 0; kk < 4; kk++) {
                    int k = k4 + kk;
                    ulonglong2 w1 = *(const ulonglong2*)(sm + A2_W1 + k * 128 + jq * 4);
                    ulonglong2 w2 = *(const ulonglong2*)(sm + A2_W1 + k * 128 + 64 + jq * 4);
                    #pragma unroll
                    for (int m = 0; m < 4; m++) {
                        float xs = (kk == 0) ? xv[m].x : (kk == 1) ? xv[m].y : (kk == 2) ? xv[m].z : xv[m].w;
                        u64 xx = pk2(xs);
                        ffma2(a1[m][0], xx, w1.x); ffma2(a1[m][1], xx, w1.y);
                        ffma2(a2[m][0], xx, w2.x); ffma2(a2[m][1], xx, w2.y);
                    }
                }
            }
            #pragma unroll
            for (int m = 0; m < 4; m++) {
                float* h1 = sm + A2_H1 + (r0 + m) * 132;
                float2 v0 = up2(a1[m][0]), v1 = up2(a1[m][1]);
                float2 v2 = up2(a2[m][0]), v3 = up2(a2[m][1]);
                h1[jq * 4 + 0] = tanhf(v0.x); h1[jq * 4 + 1] = tanhf(v0.y);
                h1[jq * 4 + 2] = tanhf(v1.x); h1[jq * 4 + 3] = tanhf(v1.y);
                h1[64 + jq * 4 + 0] = tanhf(v2.x); h1[64 + jq * 4 + 1] = tanhf(v2.y);
                h1[64 + jq * 4 + 2] = tanhf(v3.x); h1[64 + jq * 4 + 3] = tanhf(v3.y);
            }
        }

        // ---- ideal logits: warp wp handles rows wp*8..wp*8+7 ----
        for (int rr = 0; rr < 8; rr++) {
            const int row = wp * 8 + rr;
            const float* crow = context + (size_t)(row0 + row) * CTXD;
            float p0 = 0, p1 = 0, p2 = 0, p3 = 0, p4 = 0;
            #pragma unroll
            for (int ch = 0; ch < 12; ch++) {
                int k = lane + 32 * ch;
                float c = __ldg(crow + k);
                p0 = fmaf(c, sm[A2_M + 0 * 384 + k], p0);
                p1 = fmaf(c, sm[A2_M + 1 * 384 + k], p1);
                p2 = fmaf(c, sm[A2_M + 2 * 384 + k], p2);
                p3 = fmaf(c, sm[A2_M + 3 * 384 + k], p3);
                p4 = fmaf(c, sm[A2_M + 4 * 384 + k], p4);
            }
            #pragma unroll
            for (int ch = 0; ch < 2; ch++) {
                int k = lane + 32 * ch;
                float tv = sm[A2_TH + row * 68 + k];
                p0 = fmaf(tv, sm[A2_IWT + 0 * 64 + k], p0);
                p1 = fmaf(tv, sm[A2_IWT + 1 * 64 + k], p1);
                p2 = fmaf(tv, sm[A2_IWT + 2 * 64 + k], p2);
                p3 = fmaf(tv, sm[A2_IWT + 3 * 64 + k], p3);
                p4 = fmaf(tv, sm[A2_IWT + 4 * 64 + k], p4);
            }
            #pragma unroll
            for (int o = 16; o > 0; o >>= 1) {
                p0 += __shfl_xor_sync(0xffffffffu, p0, o);
                p1 += __shfl_xor_sync(0xffffffffu, p1, o);
                p2 += __shfl_xor_sync(0xffffffffu, p2, o);
                p3 += __shfl_xor_sync(0xffffffffu, p3, o);
                p4 += __shfl_xor_sync(0xffffffffu, p4, o);
            }
            if (lane == 0) {
                sm[A2_LG + row * 8 + 0] = p0 + sm[A2_IBC + 0];
                sm[A2_LG + row * 8 + 1] = p1 + sm[A2_IBC + 1];
                sm[A2_LG + row * 8 + 2] = p2 + sm[A2_IBC + 2];
                sm[A2_LG + row * 8 + 3] = p3 + sm[A2_IBC + 3];
                sm[A2_LG + row * 8 + 4] = p4 + sm[A2_IBC + 4];
            }
        }
        __syncthreads();

        // ---- e = relu(h1 @ w2^T + b2), f32x2, float4 x over k ----
        {
            ulonglong2 b2q = *(const ulonglong2*)(sm + A2_B2 + jq * 4);
            u64 ea[4][2];
            #pragma unroll
            for (int m = 0; m < 4; m++) { ea[m][0] = b2q.x; ea[m][1] = b2q.y; }
            #pragma unroll 1
            for (int k4 = 0; k4 < HIDD; k4 += 4) {
                float4 xv[4];
                #pragma unroll
                for (int m = 0; m < 4; m++)
                    xv[m] = *(const float4*)(sm + A2_H1 + (r0 + m) * 132 + k4);
                #pragma unroll
                for (int kk = 0; kk < 4; kk++) {
                    int k = k4 + kk;
                    ulonglong2 w = *(const ulonglong2*)(sm + A2_W2 + k * 64 + jq * 4);
                    #pragma unroll
                    for (int m = 0; m < 4; m++) {
                        float xs = (kk == 0) ? xv[m].x : (kk == 1) ? xv[m].y : (kk == 2) ? xv[m].z : xv[m].w;
                        u64 xx = pk2(xs);
                        ffma2(ea[m][0], xx, w.x); ffma2(ea[m][1], xx, w.y);
                    }
                }
            }
            #pragma unroll
            for (int m = 0; m < 4; m++) {
                float2 v0 = up2(ea[m][0]), v1 = up2(ea[m][1]);
                float4 ev;
                ev.x = fmaxf(v0.x, 0.f); ev.y = fmaxf(v0.y, 0.f);
                ev.z = fmaxf(v1.x, 0.f); ev.w = fmaxf(v1.y, 0.f);
                *(float4*)(g_e + (size_t)(row0 + r0 + m) * DIMV + jq * 4) = ev;
            }
        }

        // ---- softmax / theta_ideal / reductions ----
        float pi4[4];
        { float4 p = *(const float4*)(sm + A2_PI + jq * 4); pi4[0]=p.x; pi4[1]=p.y; pi4[2]=p.z; pi4[3]=p.w; }
        #pragma unroll
        for (int m = 0; m < 4; m++) {
            const int row = r0 + m;
            float l[NPR], mx = -1e30f, pw[NPR];
            #pragma unroll
            for (int p = 0; p < NPR; p++) { l[p] = sm[A2_LG + row * 8 + p]; mx = fmaxf(mx, l[p]); }
            float s = 0.f;
            #pragma unroll
            for (int p = 0; p < NPR; p++) { pw[p] = expf(l[p] - mx); s += pw[p]; }
            float inv = 1.0f / s;
            #pragma unroll
            for (int p = 0; p < NPR; p++) pw[p] *= inv;
            if (jq < NPR) out_pw[(size_t)(row0 + row) * NPR + jq] = pw[jq];

            float4 thq = *(const float4*)(sm + A2_TH + row * 68 + jq * 4);
            float tv[4] = { thq.x, thq.y, thq.z, thq.w };
            float th2 = 0, ti2 = 0, dot = 0, st = 0, fr = 0;
            #pragma unroll
            for (int e = 0; e < 4; e++) {
                int d = jq * 4 + e;
                float iv = 0.f;
                #pragma unroll
                for (int p = 0; p < NPR; p++) iv = fmaf(pw[p], sm[A2_PE + p * 64 + d], iv);
                th2 = fmaf(tv[e], tv[e], th2);
                ti2 = fmaf(iv, iv, ti2);
                dot = fmaf(tv[e], iv, dot);
                float dd = tv[e] - iv; st = fmaf(dd, dd, st);
                float df = iv - pi4[e]; fr = fmaf(df, df, fr);
            }
            st_acc += st;
            #pragma unroll
            for (int o = 1; o < 16; o <<= 1) {
                th2 += __shfl_xor_sync(0xffffffffu, th2, o);
                ti2 += __shfl_xor_sync(0xffffffffu, ti2, o);
                dot += __shfl_xor_sync(0xffffffffu, dot, o);
                fr  += __shfl_xor_sync(0xffffffffu, fr,  o);
            }
            if (jq == 0) {
                float na = sqrtf(th2), nb = sqrtf(ti2);
                float t1 = dot / ((na + EPSV) * (nb + EPSV));
                float den = fmaxf((na / (na + EPSV)) * (nb / (nb + EPSV)), EPSV);
                out_res[row0 + row] = t1 / den;
                float fq = sqrtf(fr);
                out_om[row0 + row] = tanhf(fmaf(fq, fw, fb)) * (1.0f + 0.1f * sinf(fq));
            }
        }
    }

    __syncthreads();
    sm[A2_RED + t] = st_acc;
    __syncthreads();
    for (int o = 256; o > 0; o >>= 1) {
        if (t < o) sm[A2_RED + t] += sm[A2_RED + t + o];
        __syncthreads();
    }
    if (t == 0) g_partials[blockIdx.x] = sm[A2_RED];
}

// ================= kernel C: stress, o_vec, folded gi constants ============
extern "C" __global__ void
kC(const float* __restrict__ tw, const float* __restrict__ memory,
   const float* __restrict__ ipw, const float* __restrict__ ipb,
   const float* __restrict__ outw, const float* __restrict__ outb,
   const float* __restrict__ wih_f, const float* __restrict__ bih_f,
   const float* __restrict__ wih_r, const float* __restrict__ bih_r)
{
    __shared__ float attn[MEMN], mt[DIMV], vv[DIMV], ov[DIMV], stress_s;
    const int t = threadIdx.x;
    if (t == 0) {
        float m = -1e30f;
        for (int i = 0; i < MEMN; i++) m = fmaxf(m, tw[i]);
        float s = 0, ex[MEMN];
        for (int i = 0; i < MEMN; i++) { ex[i] = expf(tw[i] - m); s += ex[i]; }
        for (int i = 0; i < MEMN; i++) attn[i] = ex[i] / s;
        float acc = 0;
        for (int i = 0; i < GRID_A; i++) acc += g_partials[i];
        g_stress = acc; stress_s = acc;
    }
    __syncthreads();
    if (t < DIMV) {
        float s = 0;
        for (int m = 0; m < MEMN; m++) s = fmaf(attn[m], memory[m * DIMV + t], s);
        mt[t] = s;
    }
    __syncthreads();
    if (t < DIMV) {
        float s = ipb[2 * DIMV + t];
        for (int d = 0; d < DIMV; d++) s = fmaf(mt[d], ipw[(2 * DIMV + t) * DIMV + d], s);
        vv[t] = s;
    }
    __syncthreads();
    if (t < DIMV) {
        float s = outb[t];
        for (int i = 0; i < DIMV; i++) s = fmaf(vv[i], outw[t * DIMV + i], s);
        ov[t] = s;
    }
    __syncthreads();
    if (t < 192) {
        float sc = 0.001f * stress_s;
        float gf = bih_f[t], gr = bih_r[t];
        for (int k = 0; k < DIMV; k++) {
            gf = fmaf(ov[k], wih_f[t * 130 + k], gf);
            gr = fmaf(ov[k], wih_r[t * 130 + k], gr);
        }
        float sf = 0, sr = 0;
        for (int k = 64; k < 128; k++) { sf += wih_f[t * 130 + k]; sr += wih_r[t * 130 + k]; }
        g_gic[0][t] = fmaf(sc, sf, gf);
        g_gic[1][t] = fmaf(sc, sr, gr);
    }
}

// ================= kernel B: both GRU directions, f32x2, 128-row tiles =====
#define B_SWI  0                        // [66][192]
#define B_SWH  12672                    // [64][192]
#define B_SGA  24960                    // 192
#define B_SGH  25152                    // 64
#define B_SX   25216                    // [128][68]
#define B_SH   33920                    // [128][68]
#define B_TOT  42624
#define SMEM_B (B_TOT * 4)

extern "C" __global__ void __launch_bounds__(512)
kB(const float* __restrict__ wih_f, const float* __restrict__ whh_f,
   const float* __restrict__ bhh_f,
   const float* __restrict__ wih_r, const float* __restrict__ whh_r,
   const float* __restrict__ bhh_r,
   const float* __restrict__ hprev, const float* __restrict__ theta,
   const float* __restrict__ res_in, const float* __restrict__ om_in,
   float* __restrict__ hout, float* __restrict__ thout,
   float* __restrict__ eout, int ntiles, int Btot)
{
    extern __shared__ float sm[];
    const int t = threadIdx.x;
    const int dir = blockIdx.x & 1;

    const float* wih = dir ? wih_r : wih_f;
    const float* whh = dir ? whh_r : whh_f;
    const float* bhh = dir ? bhh_r : bhh_f;
    const float* hp  = hprev + (size_t)dir * Btot * DIMV;
    float* ho        = hout  + (size_t)dir * Btot * DIMV;

    for (int i = t; i < 192 * 66; i += 512) {
        int j = i / 66, c = i % 66;
        sm[B_SWI + c * 192 + j] = wih[j * 130 + 64 + c];
    }
    for (int i = t; i < 192 * 64; i += 512) {
        int j = i / 64, c = i % 64;
        sm[B_SWH + c * 192 + j] = whh[j * 64 + c];
    }
    if (t < 192) {
        float v = g_gic[dir][t];
        if (t < 128) v += bhh[t];
        sm[B_SGA + t] = v;
    }
    if (t < 64) sm[B_SGH + t] = bhh[128 + t];
    __syncthreads();

    const float sc = 0.001f * g_stress;
    const int rb = t >> 4, jq = t & 15;
    const int r0 = rb * 4;
    const float lam = 0.7f, oml = 0.3f;
    const int nblk = gridDim.x >> 1;

    for (int tile = blockIdx.x >> 1; tile < ntiles; tile += nblk) {
        __syncthreads();
        const int row0 = tile * 128;
        {
            const float4* e4 = (const float4*)(g_e + (size_t)row0 * DIMV);
            const float4* h4 = (const float4*)(hp  + (size_t)row0 * DIMV);
            for (int i = t; i < 128 * 16; i += 512) {
                int r = i / 16, c = i % 16;
                ((float4*)(sm + B_SX + r * 68))[c] = e4[i];
                ((float4*)(sm + B_SH + r * 68))[c] = h4[i];
            }
            if (t < 128) {
                sm[B_SX + t * 68 + 64] = res_in[row0 + t];
                sm[B_SX + t * 68 + 65] = om_in[row0 + t];
            }
        }
        __syncthreads();

        u64 ar[4][2], az[4][2], an[4][2], ah[4][2];
        {
            ulonglong2 ia = *(const ulonglong2*)(sm + B_SGA + jq * 4);
            ulonglong2 iz = *(const ulonglong2*)(sm + B_SGA + 64 + jq * 4);
            ulonglong2 in_ = *(const ulonglong2*)(sm + B_SGA + 128 + jq * 4);
            ulonglong2 ih = *(const ulonglong2*)(sm + B_SGH + jq * 4);
            #pragma unroll
            for (int m = 0; m < 4; m++) {
                ar[m][0] = ia.x;  ar[m][1] = ia.y;
                az[m][0] = iz.x;  az[m][1] = iz.y;
                an[m][0] = in_.x; an[m][1] = in_.y;
                ah[m][0] = ih.x;  ah[m][1] = ih.y;
            }
        }

        #pragma unroll 1
        for (int k4 = 0; k4 < 64; k4 += 2) {
            float2 xv[4], hv[4];
            #pragma unroll
            for (int m = 0; m < 4; m++) {
                xv[m] = *(const float2*)(sm + B_SX + (r0 + m) * 68 + k4);
                hv[m] = *(const float2*)(sm + B_SH + (r0 + m) * 68 + k4);
            }
            #pragma unroll
            for (int kk = 0; kk < 2; kk++) {
                const int k = k4 + kk;
                ulonglong2 wr_i = *(const ulonglong2*)(sm + B_SWI + k * 192 + jq * 4);
                ulonglong2 wz_i = *(const ulonglong2*)(sm + B_SWI + k * 192 + 64 + jq * 4);
                ulonglong2 wn_i = *(const ulonglong2*)(sm + B_SWI + k * 192 + 128 + jq * 4);
                ulonglong2 wr_h = *(const ulonglong2*)(sm + B_SWH + k * 192 + jq * 4);
                ulonglong2 wz_h = *(const ulonglong2*)(sm + B_SWH + k * 192 + 64 + jq * 4);
                ulonglong2 wn_h = *(const ulonglong2*)(sm + B_SWH + k * 192 + 128 + jq * 4);
                #pragma unroll
                for (int m = 0; m < 4; m++) {
                    u64 xx = pk2(kk ? xv[m].y : xv[m].x);
                    u64 hh = pk2(kk ? hv[m].y : hv[m].x);
                    ffma2(ar[m][0], xx, wr_i.x); ffma2(ar[m][1], xx, wr_i.y);
                    ffma2(ar[m][0], hh, wr_h.x); ffma2(ar[m][1], hh, wr_h.y);
                    ffma2(az[m][0], xx, wz_i.x); ffma2(az[m][1], xx, wz_i.y);
                    ffma2(az[m][0], hh, wz_h.x); ffma2(az[m][1], hh, wz_h.y);
                    ffma2(an[m][0], xx, wn_i.x); ffma2(an[m][1], xx, wn_i.y);
                    ffma2(ah[m][0], hh, wn_h.x); ffma2(ah[m][1], hh, wn_h.y);
                }
            }
        }
        #pragma unroll
        for (int k = 64; k < 66; k++) {
            ulonglong2 wr_i = *(const ulonglong2*)(sm + B_SWI + k * 192 + jq * 4);
            ulonglong2 wz_i = *(const ulonglong2*)(sm + B_SWI + k * 192 + 64 + jq * 4);
            ulonglong2 wn_i = *(const ulonglong2*)(sm + B_SWI + k * 192 + 128 + jq * 4);
            #pragma unroll
            for (int m = 0; m < 4; m++) {
                u64 xx = pk2(sm[B_SX + (r0 + m) * 68 + k]);
                ffma2(ar[m][0], xx, wr_i.x); ffma2(ar[m][1], xx, wr_i.y);
                ffma2(az[m][0], xx, wz_i.x); ffma2(az[m][1], xx, wz_i.y);
                ffma2(an[m][0], xx, wn_i.x); ffma2(an[m][1], xx, wn_i.y);
            }
        }

        #pragma unroll
        for (int m = 0; m < 4; m++) {
            const int row = row0 + r0 + m;
            float rv[4], zv[4], nv[4], hv2[4];
            { float2 a = up2(ar[m][0]), b = up2(ar[m][1]); rv[0]=a.x; rv[1]=a.y; rv[2]=b.x; rv[3]=b.y; }
            { float2 a = up2(az[m][0]), b = up2(az[m][1]); zv[0]=a.x; zv[1]=a.y; zv[2]=b.x; zv[3]=b.y; }
            { float2 a = up2(an[m][0]), b = up2(an[m][1]); nv[0]=a.x; nv[1]=a.y; nv[2]=b.x; nv[3]=b.y; }
            { float2 a = up2(ah[m][0]), b = up2(ah[m][1]); hv2[0]=a.x; hv2[1]=a.y; hv2[2]=b.x; hv2[3]=b.y; }
            float4 hn4; float* hn = (float*)&hn4;
            #pragma unroll
            for (int e = 0; e < 4; e++) {
                float rg = 1.0f / (1.0f + expf(-rv[e]));
                float zg = 1.0f / (1.0f + expf(-zv[e]));
                float ng = tanhf(fmaf(rg, hv2[e], nv[e]));
                float hvp = sm[B_SH + (r0 + m) * 68 + jq * 4 + e];
                hn[e] = fmaf(zg, hvp - ng, ng);
            }
            const size_t ob = (size_t)row * DIMV + jq * 4;
            *(float4*)(ho + ob) = hn4;
            if (dir == 0) {
                float4 th = *(const float4*)(theta + ob);
                float4 tn;
                tn.x = fmaf(lam, hn4.x, oml * th.x); tn.y = fmaf(lam, hn4.y, oml * th.y);
                tn.z = fmaf(lam, hn4.z, oml * th.z); tn.w = fmaf(lam, hn4.w, oml * th.w);
                *(float4*)(thout + ob) = tn;
                float4 ev = *(const float4*)(sm + B_SX + (r0 + m) * 68 + jq * 4);
                ev.x += sc; ev.y += sc; ev.z += sc; ev.w += sc;
                *(float4*)(eout + ob) = ev;
            }
        }
    }
}

// ================= launch =================
extern "C" void kernel_launch(void* const* d_in, const int* in_sizes, int n_in,
                              void* d_out, int out_size)
{
    const float* theta     = (const float*)d_in[0];
    const float* context   = (const float*)d_in[1];
    const float* h_prev    = (const float*)d_in[2];
    const float* memory    = (const float*)d_in[3];
    const float* tw        = (const float*)d_in[4];
    const float* ipw       = (const float*)d_in[5];
    const float* ipb       = (const float*)d_in[6];
    const float* outw      = (const float*)d_in[7];
    const float* outb      = (const float*)d_in[8];
    const float* emo_w1    = (const float*)d_in[9];
    const float* emo_b1    = (const float*)d_in[10];
    const float* emo_w2    = (const float*)d_in[11];
    const float* emo_b2    = (const float*)d_in[12];
    const float* prime_emb = (const float*)d_in[13];
    const float* ctx_w     = (const float*)d_in[14];
    const float* ctx_b     = (const float*)d_in[15];
    const float* ideal_w   = (const float*)d_in[16];
    const float* ideal_b   = (const float*)d_in[17];
    const float* wih_f     = (const float*)d_in[18];
    const float* whh_f     = (const float*)d_in[19];
    const float* bih_f     = (const float*)d_in[20];
    const float* bhh_f     = (const float*)d_in[21];
    const float* wih_r     = (const float*)d_in[22];
    const float* whh_r     = (const float*)d_in[23];
    const float* bih_r     = (const float*)d_in[24];
    const float* bhh_r     = (const float*)d_in[25];
    const float* freq_w    = (const float*)d_in[26];
    const float* freq_b    = (const float*)d_in[27];
    const float* prev_id   = (const float*)d_in[28];

    const int B = in_sizes[0] / DIMV;
    const int ntiles = B / 128;

    float* out = (float*)d_out;
    float* o_thn = out;
    float* o_h   = out + (size_t)B * DIMV;
    float* o_e   = out + (size_t)3 * B * DIMV;
    float* o_res = out + (size_t)4 * B * DIMV;
    float* o_om  = o_res + B;
    float* o_pw  = o_om + B;

    cudaFuncSetAttribute((const void*)kA2, cudaFuncAttributeMaxDynamicSharedMemorySize, SMEM_A2);
    cudaFuncSetAttribute((const void*)kB,  cudaFuncAttributeMaxDynamicSharedMemorySize, SMEM_B);

    kC0<<<NPR, CTXD>>>(ideal_w, ctx_w, ctx_b, ideal_b);
    kA2<<<GRID_A, 512, SMEM_A2>>>(theta, context, emo_w1, emo_b1, emo_w2, emo_b2,
                                  prime_emb, ideal_w, prev_id,
                                  freq_w, freq_b, o_res, o_om, o_pw, ntiles);
    kC<<<1, 192>>>(tw, memory, ipw, ipb, outw, outb, wih_f, bih_f, wih_r, bih_r);
    kB<<<296, 512, SMEM_B>>>(wih_f, whh_f, bhh_f, wih_r, whh_r, bhh_r,
                             h_prev, theta, o_res, o_om,
                             o_h, o_thn, o_e, ntiles, B);
}